// round 11
// baseline (speedup 1.0000x reference)
#include <cuda_runtime.h>
#include <cuda_fp16.h>
#include <math.h>
#include <stdint.h>

#define L  1024
#define D  512
#define NH 8
#define DA 32
#define AH 256
#define DH 4096
#define FF 2048

// -------- scratch --------
__device__ __half g_hx[L * D];
__device__ __half g_xnh[L * D];
__device__ __half g_hqw[D * AH];
__device__ __half g_hkw[D * AH];
__device__ __half g_hvw[D * DH];
__device__ __half g_hw1[DH * FF];
__device__ __half g_hw2[FF * D];
__device__ __half g_yh[(size_t)L * DH];
__device__ __half g_h1h[L * FF];
__device__ __half g_qh[NH * L * DA];
__device__ __half g_kh[NH * L * DA];
__device__ __half g_vh[NH * L * D];
__device__ float g_den[NH * L];
__device__ float g_qkvh[NH * L * D];
__device__ float g_part[4 * L * D];
__device__ float g_parth[2 * L * FF];
__device__ float g_partq[4 * L * AH];
__device__ float g_partk[4 * L * AH];

__device__ __forceinline__ unsigned f2tf32(float v) {
    unsigned o;
    asm volatile("cvt.rna.tf32.f32 %0, %1;" : "=r"(o) : "f"(v));
    return o;
}
__device__ __forceinline__ float rnd(float v) { return __uint_as_float(f2tf32(v)); }

__device__ __forceinline__ void cpa16s(unsigned sa, const void* g) {
    asm volatile("cp.async.cg.shared.global [%0], [%1], 16;\n" :: "r"(sa), "l"(g));
}
#define CP_COMMIT() asm volatile("cp.async.commit_group;\n" ::: "memory")
#define CP_WAIT2()  asm volatile("cp.async.wait_group 2;\n" ::: "memory")

__device__ __forceinline__ void ldsm4(unsigned& r0, unsigned& r1, unsigned& r2, unsigned& r3,
                                      unsigned addr) {
    asm volatile("ldmatrix.sync.aligned.m8n8.x4.shared.b16 {%0,%1,%2,%3}, [%4];"
                 : "=r"(r0), "=r"(r1), "=r"(r2), "=r"(r3) : "r"(addr));
}
__device__ __forceinline__ void ldsm4t(unsigned& r0, unsigned& r1, unsigned& r2, unsigned& r3,
                                       unsigned addr) {
    asm volatile("ldmatrix.sync.aligned.m8n8.x4.trans.shared.b16 {%0,%1,%2,%3}, [%4];"
                 : "=r"(r0), "=r"(r1), "=r"(r2), "=r"(r3) : "r"(addr));
}

#define MMA_F16(c0,c1,c2,c3,a0,a1,a2,a3,b0,b1) \
    asm volatile("mma.sync.aligned.m16n8k16.row.col.f32.f16.f16.f32 " \
        "{%0,%1,%2,%3}, {%4,%5,%6,%7}, {%8,%9}, {%0,%1,%2,%3};" \
        : "+f"(c0), "+f"(c1), "+f"(c2), "+f"(c3) \
        : "r"(a0), "r"(a1), "r"(a2), "r"(a3), "r"(b0), "r"(b1))

__device__ __forceinline__ float2 block_reduce2(float a, float b) {
    __shared__ float2 sh[16];
    int tid = threadIdx.x;
#pragma unroll
    for (int o = 16; o > 0; o >>= 1) {
        a += __shfl_down_sync(0xffffffffu, a, o);
        b += __shfl_down_sync(0xffffffffu, b, o);
    }
    int wid = tid >> 5, lane = tid & 31;
    int nw = blockDim.x >> 5;
    if (lane == 0) sh[wid] = make_float2(a, b);
    __syncthreads();
    if (wid == 0) {
        float2 v = (lane < nw) ? sh[lane] : make_float2(0.f, 0.f);
        a = v.x; b = v.y;
#pragma unroll
        for (int o = 8; o > 0; o >>= 1) {
            a += __shfl_down_sync(0xffffffffu, a, o);
            b += __shfl_down_sync(0xffffffffu, b, o);
        }
        if (lane == 0) sh[0] = make_float2(a, b);
    }
    __syncthreads();
    return sh[0];
}

// -------- fused: fp16 conversion of weights+x AND LN0(x)->fp16 --------
__global__ void conv_ln0(const float* __restrict__ qw, const float* __restrict__ kw,
                         const float* __restrict__ vw, const float* __restrict__ w1,
                         const float* __restrict__ w2, const float* __restrict__ x,
                         const float* __restrict__ ln0w, const float* __restrict__ ln0b,
                         __half* hqw, __half* hkw, __half* hvw, __half* hw1, __half* hw2,
                         __half* hx, __half* xnh)
{
    int t = blockIdx.x;
    int tid = threadIdx.x;
    if (t < 12032) {
        int q = t * 256 + tid;
        const float4* s; __half* d; int off;
        if (q < 32768)        { s = (const float4*)qw; d = hqw; off = q; }
        else if (q < 65536)   { s = (const float4*)kw; d = hkw; off = q - 32768; }
        else if (q < 589824)  { s = (const float4*)vw; d = hvw; off = q - 65536; }
        else if (q < 2686976) { s = (const float4*)w1; d = hw1; off = q - 589824; }
        else if (q < 2949120) { s = (const float4*)w2; d = hw2; off = q - 2686976; }
        else                  { s = (const float4*)x;  d = hx;  off = q - 2949120; }
        float4 v = s[off];
        __half2* d2 = (__half2*)d;
        d2[off * 2]     = __floats2half2_rn(v.x, v.y);
        d2[off * 2 + 1] = __floats2half2_rn(v.z, v.w);
        return;
    }
    int l = t - 12032;
    const float* row = x + (size_t)l * D;
    float v0 = row[tid], v1 = row[tid + 256];
    float2 r = block_reduce2(v0 + v1, v0 * v0 + v1 * v1);
    float mu = r.x * (1.0f / D);
    float var = r.y * (1.0f / D) - mu * mu;
    float rs = rsqrtf(var + 1e-5f);
    xnh[(size_t)l * D + tid]       = __float2half_rn((v0 - mu) * rs * ln0w[tid] + ln0b[tid]);
    xnh[(size_t)l * D + tid + 256] = __float2half_rn((v1 - mu) * rs * ln0w[tid + 256] + ln0b[tid + 256]);
}

// ========== fp16 tensor GEMM: 128x128x32 tiles, 4 warps (64x64), 4 stages ==========
#define HG_ASTR 40
#define HG_BSTR 136
#define HG_ABYT (128 * HG_ASTR * 2)
#define HG_STG  (HG_ABYT + 32 * HG_BSTR * 2)
#define HG_SMEM (4 * HG_STG)

template<int EPI, int PERM, int MODE, int ROUND, int HOUT>
__global__ void __launch_bounds__(128, 2) hgemm(
    const __half* __restrict__ A, const __half* __restrict__ B,
    const float* __restrict__ bias, void* __restrict__ Cv,
    const __half* __restrict__ B2, void* __restrict__ C2v,
    int M, int N, int K, int lda, int ldb)
{
    extern __shared__ char smemc[];
    uint32_t sbase = (uint32_t)__cvta_generic_to_shared(smemc);

    float* C = (float*)Cv;
    int z = blockIdx.z;
    if (MODE == 2) {
        A += (size_t)z * K;
        B += (size_t)z * K * ldb;
        C += (size_t)z * M * N;
    } else if (MODE == 3) {
        int set = z >> 2, zz = z & 3;
        if (set) { B = B2; C = (float*)C2v; }
        A += (size_t)zz * K;
        B += (size_t)zz * K * ldb;
        C += (size_t)zz * M * N;
    }

    int tid = threadIdx.x;
    int wid = tid >> 5, lane = tid & 31;
    int group = lane >> 2, tg = lane & 3;
    int warp_m = wid >> 1, warp_n = wid & 1;
    int m0 = blockIdx.y * 128, n0 = blockIdx.x * 128;
    int kTiles = K / 32;

    const __half* Ab = A + (size_t)(m0 + tid) * lda;
    int br = tid >> 2, bc = (tid & 3) * 32;
    const __half* Bb = B + n0 + bc;

    uint32_t laA = ((lane & 15) * HG_ASTR + ((lane >> 4) << 3)) * 2;
    uint32_t laB = ((lane & 15) * HG_BSTR + ((lane >> 4) << 3)) * 2;
    uint32_t afw = (uint32_t)(warp_m * 64 * HG_ASTR * 2) + laA;
    uint32_t bfw = (uint32_t)(warp_n * 64 * 2) + laB;

    float c[4][8][4];
#pragma unroll
    for (int i = 0; i < 4; i++)
#pragma unroll
        for (int j = 0; j < 8; j++)
#pragma unroll
            for (int r = 0; r < 4; r++) c[i][j][r] = 0.f;

#pragma unroll
    for (int s = 0; s < 3; s++) {
        if (s < kTiles) {
            uint32_t sA = sbase + s * HG_STG;
            uint32_t sB = sA + HG_ABYT;
#pragma unroll
            for (int cc = 0; cc < 4; cc++)
                cpa16s(sA + (tid * HG_ASTR + cc * 8) * 2, Ab + s * 32 + cc * 8);
#pragma unroll
            for (int cc = 0; cc < 4; cc++)
                cpa16s(sB + (br * HG_BSTR + bc + cc * 8) * 2,
                       Bb + (size_t)(s * 32 + br) * ldb + cc * 8);
        }
        CP_COMMIT();
    }
    CP_WAIT2();
    __syncthreads();

    for (int t = 0; t < kTiles; t++) {
        int tp = t + 3;
        if (tp < kTiles) {
            int ps = tp & 3;
            uint32_t sA = sbase + ps * HG_STG;
            uint32_t sB = sA + HG_ABYT;
#pragma unroll
            for (int cc = 0; cc < 4; cc++)
                cpa16s(sA + (tid * HG_ASTR + cc * 8) * 2, Ab + tp * 32 + cc * 8);
#pragma unroll
            for (int cc = 0; cc < 4; cc++)
                cpa16s(sB + (br * HG_BSTR + bc + cc * 8) * 2,
                       Bb + (size_t)(tp * 32 + br) * ldb + cc * 8);
        }
        CP_COMMIT();

        uint32_t aSt = sbase + (t & 3) * HG_STG + afw;
        uint32_t bSt = sbase + (t & 3) * HG_STG + HG_ABYT + bfw;

        unsigned a[2][4][4], b[2][8][2];
#pragma unroll
        for (int kk = 0; kk < 2; kk++) {
#pragma unroll
            for (int mt = 0; mt < 4; mt++)
                ldsm4(a[kk][mt][0], a[kk][mt][1], a[kk][mt][2], a[kk][mt][3],
                      aSt + (unsigned)((mt * 16 * HG_ASTR + kk * 16) * 2));
#pragma unroll
            for (int p = 0; p < 4; p++) {
                unsigned u0, u1, u2, u3;
                ldsm4t(u0, u1, u2, u3,
                       bSt + (unsigned)((p * 16) * 2 + (kk * 16 * HG_BSTR) * 2));
                b[kk][2 * p][0] = u0;     b[kk][2 * p][1] = u1;
                b[kk][2 * p + 1][0] = u2; b[kk][2 * p + 1][1] = u3;
            }
        }
#pragma unroll
        for (int kk = 0; kk < 2; kk++)
#pragma unroll
            for (int mt = 0; mt < 4; mt++)
#pragma unroll
                for (int nt = 0; nt < 8; nt++)
                    MMA_F16(c[mt][nt][0], c[mt][nt][1], c[mt][nt][2], c[mt][nt][3],
                            a[kk][mt][0], a[kk][mt][1], a[kk][mt][2], a[kk][mt][3],
                            b[kk][nt][0], b[kk][nt][1]);

        CP_WAIT2();
        __syncthreads();
    }

#pragma unroll
    for (int mt = 0; mt < 4; mt++) {
#pragma unroll
        for (int nt = 0; nt < 8; nt++) {
#pragma unroll
            for (int r = 0; r < 4; r++) {
                int m = m0 + warp_m * 64 + mt * 16 + group + (r >> 1) * 8;
                int n = n0 + warp_n * 64 + nt * 8 + tg * 2 + (r & 1);
                float v = c[mt][nt][r];
                if (EPI == 2) v = v + bias[n];
                else if (EPI == 3) v = fmaxf(v + bias[n], 0.f);
                if (ROUND) v = rnd(v);
                if (PERM == 0) {
                    C[(size_t)m * N + n] = v;
                } else {
                    int h = n & 7, inner = n >> 3;
                    if (HOUT)
                        ((__half*)Cv)[((size_t)(h * M + m)) * (N >> 3) + inner] = __float2half_rn(v);
                    else
                        C[((size_t)(h * M + m)) * (N >> 3) + inner] = v;
                }
            }
        }
    }
}

// -------- split-K reduce for q/k: fp16(exp(clip(sum+bias) - 4)), head-major --------
__global__ void reduce_qk(const float* __restrict__ pq, const float* __restrict__ pk,
                          const float* __restrict__ qb, const float* __restrict__ kb,
                          __half* __restrict__ qh, __half* __restrict__ kh)
{
    int set = blockIdx.y;
    const float* p   = set ? pk : pq;
    const float* bia = set ? kb : qb;
    __half* o = set ? kh : qh;
    int i = blockIdx.x * 256 + threadIdx.x;
    int m = i >> 8, n = i & 255;
    float s = p[i] + p[i + 262144] + p[i + 524288] + p[i + 786432] + bia[n];
    s = expf(fminf(fmaxf(s, -10.f), 10.f) - 4.0f);
    int h = n & 7, inner = n >> 3;
    o[((size_t)(h * L + m)) * DA + inner] = __float2half_rn(s);
}

// ================= fused flash attention, fp16, 512 threads, d-tile 256 =================
// grid (2 dtiles, 8 iblocks, 8 heads) = 128 CTAs = 1 wave. Warps 4x4.
#define AQ_OFF 0
#define AK_OFF 10240
#define AV_OFF 30720
#define AS_OFF 98304
#define ADN_OFF 133120
#define ATTN_SMEM 135168
#define KSTR 40
#define VSTR 264
#define SSTR 136

__global__ void __launch_bounds__(512, 1) attn_kernel(
    const __half* __restrict__ qhp, const __half* __restrict__ khp,
    const __half* __restrict__ vhp, float* __restrict__ qkvh,
    float* __restrict__ den)
{
    extern __shared__ char smc[];
    uint32_t sb = (uint32_t)__cvta_generic_to_shared(smc);
    float* dn = (float*)(smc + ADN_OFF);

    int d0 = blockIdx.x * 256;
    int i  = 7 - blockIdx.y;
    int h  = blockIdx.z;

    int tid = threadIdx.x, lane = tid & 31, wid = tid >> 5;
    int group = lane >> 2, tg = lane & 3;
    int ws_m = wid >> 2, ws_n = wid & 3;   // 4x4 warp grid

    const __half* Qg = qhp + ((size_t)h * L + i * 128) * DA;
    const __half* Kg = khp + (size_t)h * L * DA;
    const __half* Vg = vhp + (size_t)h * L * D + d0;

    dn[tid] = 0.f;

    int qr = tid >> 2, qc = (tid & 3) * 8;         // Q/K: 1 cpa per thread
    int vr = tid >> 2, vq = (tid & 3) * 64;        // V: 8 cpa per thread

    // prologue: Q + K0 (one group)
    cpa16s(sb + AQ_OFF + (qr * KSTR + qc) * 2, Qg + qr * DA + qc);
    cpa16s(sb + AK_OFF + (qr * KSTR + qc) * 2, Kg + qr * DA + qc);
    CP_COMMIT();

    float oc[2][8][4];
#pragma unroll
    for (int a = 0; a < 2; a++)
#pragma unroll
        for (int b = 0; b < 8; b++)
#pragma unroll
            for (int r = 0; r < 4; r++) oc[a][b][r] = 0.f;
    float dpart[4];
#pragma unroll
    for (int a = 0; a < 4; a++) dpart[a] = 0.f;

    uint32_t laK = ((lane & 15) * KSTR + ((lane >> 4) << 3)) * 2;
    uint32_t laV = ((lane & 15) * VSTR + ((lane >> 4) << 3)) * 2;
    uint32_t laS = ((lane & 15) * SSTR + ((lane >> 4) << 3)) * 2;
    uint32_t qfb = sb + AQ_OFF + (uint32_t)(ws_m * 32 * KSTR * 2) + laK;
    uint32_t sfb = sb + AS_OFF + (uint32_t)(ws_m * 32 * SSTR * 2) + laS;
    uint32_t vfb = sb + AV_OFF + (uint32_t)(ws_n * 64 * 2) + laV;

    for (int j = 0; j <= i; j++) {
        int buf = j & 1;
        // issue V[j] (single buffer)
        {
            const __half* vg = Vg + (size_t)j * 128 * D;
#pragma unroll
            for (int kk = 0; kk < 8; kk++)
                cpa16s(sb + AV_OFF + (vr * VSTR + vq + kk * 8) * 2,
                       vg + (size_t)vr * D + vq + kk * 8);
            CP_COMMIT();
        }
        // issue K[j+1]
        if (j < i) {
            const __half* kg = Kg + (size_t)(j + 1) * 128 * DA;
            cpa16s(sb + AK_OFF + (buf ^ 1) * 10240 + (qr * KSTR + qc) * 2,
                   kg + qr * DA + qc);
            CP_COMMIT();
        }
        // ensure K[j] (and older) complete; V[j] (+K[j+1]) may fly
        if (j < i) asm volatile("cp.async.wait_group 2;\n" ::: "memory");
        else       asm volatile("cp.async.wait_group 1;\n" ::: "memory");
        __syncthreads();

        // ---- S = Q K_j^T ----
        float sc[2][4][4];
#pragma unroll
        for (int a = 0; a < 2; a++)
#pragma unroll
            for (int b = 0; b < 4; b++)
#pragma unroll
                for (int r = 0; r < 4; r++) sc[a][b][r] = 0.f;

        uint32_t kb0 = sb + AK_OFF + (uint32_t)(buf * 10240)
                     + (uint32_t)(ws_n * 32 * KSTR * 2) + laK;
#pragma unroll
        for (int kc = 0; kc < 2; kc++) {
            unsigned qa[2][4], kb[4][2];
#pragma unroll
            for (int mt = 0; mt < 2; mt++)
                ldsm4(qa[mt][0], qa[mt][1], qa[mt][2], qa[mt][3],
                      qfb + (unsigned)((mt * 16 * KSTR + kc * 16) * 2));
#pragma unroll
            for (int p = 0; p < 2; p++) {
                unsigned u0, u1, u2, u3;
                ldsm4(u0, u1, u2, u3, kb0 + (unsigned)((p * 16 * KSTR + kc * 16) * 2));
                kb[2 * p][0] = u0;     kb[2 * p][1] = u2;
                kb[2 * p + 1][0] = u1; kb[2 * p + 1][1] = u3;
            }
#pragma unroll
            for (int mt = 0; mt < 2; mt++)
#pragma unroll
                for (int nt = 0; nt < 4; nt++)
                    MMA_F16(sc[mt][nt][0], sc[mt][nt][1], sc[mt][nt][2], sc[mt][nt][3],
                            qa[mt][0], qa[mt][1], qa[mt][2], qa[mt][3],
                            kb[nt][0], kb[nt][1]);
        }

        // ---- mask / fp16-round / den partials / stage S ----
        bool diag = (j == i);
#pragma unroll
        for (int mt = 0; mt < 2; mt++) {
#pragma unroll
            for (int rp = 0; rp < 2; rp++) {
                int row = ws_m * 32 + mt * 16 + group + rp * 8;
#pragma unroll
                for (int nt = 0; nt < 4; nt++) {
                    int colb = ws_n * 32 + nt * 8 + tg * 2;
                    float v0 = sc[mt][nt][rp * 2], v1 = sc[mt][nt][rp * 2 + 1];
                    if (diag) {
                        if (colb > row) v0 = 0.f;
                        if (colb + 1 > row) v1 = 0.f;
                    }
                    __half2 hv = __floats2half2_rn(v0, v1);
                    float2 fb = __half22float2(hv);
                    dpart[mt * 2 + rp] += fb.x + fb.y;
                    *(__half2*)(smc + AS_OFF + ((size_t)row * SSTR + colb) * 2) = hv;
                }
            }
        }
        // V[j] must be complete before S@V (K[j+1] may still fly)
        if (j < i) asm volatile("cp.async.wait_group 1;\n" ::: "memory");
        else       asm volatile("cp.async.wait_group 0;\n" ::: "memory");
        __syncthreads();

        // ---- O += S @ V_j ----
#pragma unroll
        for (int kc = 0; kc < 8; kc++) {
            unsigned sa[2][4], vb[8][2];
#pragma unroll
            for (int mt = 0; mt < 2; mt++)
                ldsm4(sa[mt][0], sa[mt][1], sa[mt][2], sa[mt][3],
                      sfb + (unsigned)((mt * 16 * SSTR + kc * 16) * 2));
#pragma unroll
            for (int p = 0; p < 4; p++) {
                unsigned u0, u1, u2, u3;
                ldsm4t(u0, u1, u2, u3,
                       vfb + (unsigned)((kc * 16 * VSTR + p * 16) * 2));
                vb[2 * p][0] = u0;     vb[2 * p][1] = u1;
                vb[2 * p + 1][0] = u2; vb[2 * p + 1][1] = u3;
            }
#pragma unroll
            for (int mt = 0; mt < 2; mt++)
#pragma unroll
                for (int nt = 0; nt < 8; nt++)
                    MMA_F16(oc[mt][nt][0], oc[mt][nt][1], oc[mt][nt][2], oc[mt][nt][3],
                            sa[mt][0], sa[mt][1], sa[mt][2], sa[mt][3],
                            vb[nt][0], vb[nt][1]);
        }
        __syncthreads();   // protect S and V buffers for next iteration
    }

    // ---- write O ----
#pragma unroll
    for (int mt = 0; mt < 2; mt++)
#pragma unroll
        for (int rp = 0; rp < 2; rp++) {
            int m = i * 128 + ws_m * 32 + mt * 16 + group + rp * 8;
#pragma unroll
            for (int nt = 0; nt < 8; nt++) {
                int dd = d0 + ws_n * 64 + nt * 8 + tg * 2;
                *(float2*)&qkvh[((size_t)h * L + m) * D + dd] =
                    make_float2(oc[mt][nt][rp * 2], oc[mt][nt][rp * 2 + 1]);
            }
        }

    // ---- den ----
#pragma unroll
    for (int q = 0; q < 4; q++) {
        float v = dpart[q];
        v += __shfl_xor_sync(0xffffffffu, v, 1, 4);
        v += __shfl_xor_sync(0xffffffffu, v, 2, 4);
        dpart[q] = v;
    }
    if (tg == 0) {
#pragma unroll
        for (int mt = 0; mt < 2; mt++)
#pragma unroll
            for (int rp = 0; rp < 2; rp++) {
                int row = ws_m * 32 + mt * 16 + group + rp * 8;
                dn[ws_n * 128 + row] = dpart[mt * 2 + rp];
            }
    }
    __syncthreads();
    if (blockIdx.x == 0 && tid < 128)
        den[h * L + i * 128 + tid] = dn[tid] + dn[128 + tid] + dn[256 + tid] + dn[384 + tid];
}

// -------- y = x + LN1(qkv/den), fp16 output --------
__global__ void y_kernel(const float* __restrict__ x, const float* __restrict__ qkvh,
                         const float* __restrict__ den, const float* __restrict__ w,
                         const float* __restrict__ b, __half* __restrict__ y)
{
    int l = blockIdx.x, tid = threadIdx.x;
    float t[8];
    float s = 0.f, s2 = 0.f;
#pragma unroll
    for (int r = 0; r < 8; r++) {
        int j = tid + r * 512;
        int h = j & 7, d = j >> 3;
        float v = qkvh[((size_t)(h * L + l)) * D + d] / den[h * L + l];
        t[r] = v; s += v; s2 += v * v;
    }
    float2 red = block_reduce2(s, s2);
    float mu = red.x * (1.0f / DH);
    float rs = rsqrtf(red.y * (1.0f / DH) - mu * mu + 1e-5f);
#pragma unroll
    for (int r = 0; r < 8; r++) {
        int j = tid + r * 512;
        y[(size_t)l * DH + j] =
            __float2half_rn(x[(size_t)l * D + (j >> 3)] + (t[r] - mu) * rs * w[j] + b[j]);
    }
}

__global__ void reduce_h1(const float* __restrict__ part, const float* __restrict__ b1,
                          __half* __restrict__ h1)
{
    int q = blockIdx.x * 256 + threadIdx.x;
    const float4* p = (const float4*)part;
    float4 v0 = p[q];
    float4 v1 = p[q + (L * FF / 4)];
    float4 bb = ((const float4*)b1)[q & (FF / 4 - 1)];
    __half2* H = (__half2*)h1;
    H[q * 2]     = __floats2half2_rn(fmaxf(v0.x + v1.x + bb.x, 0.f),
                                     fmaxf(v0.y + v1.y + bb.y, 0.f));
    H[q * 2 + 1] = __floats2half2_rn(fmaxf(v0.z + v1.z + bb.z, 0.f),
                                     fmaxf(v0.w + v1.w + bb.w, 0.f));
}

__global__ void reduce_out(const float* __restrict__ part, const float* __restrict__ b2,
                           const float* __restrict__ x, float* __restrict__ out)
{
    int q = blockIdx.x * 256 + threadIdx.x;
    const float4* p = (const float4*)part;
    float4 v0 = p[q];
    float4 v1 = p[q + 131072];
    float4 v2 = p[q + 262144];
    float4 v3 = p[q + 393216];
    float4 bb = ((const float4*)b2)[q & 127];
    float4 xx = ((const float4*)x)[q];
    float4 o;
    o.x = fmaxf(v0.x + v1.x + v2.x + v3.x + bb.x, 0.f) + xx.x;
    o.y = fmaxf(v0.y + v1.y + v2.y + v3.y + bb.y, 0.f) + xx.y;
    o.z = fmaxf(v0.z + v1.z + v2.z + v3.z + bb.z, 0.f) + xx.z;
    o.w = fmaxf(v0.w + v1.w + v2.w + v3.w + bb.w, 0.f) + xx.w;
    ((float4*)out)[q] = o;
}

extern "C" void kernel_launch(void* const* d_in, const int* in_sizes, int n_in,
                              void* d_out, int out_size)
{
    const float* x    = (const float*)d_in[0];
    const float* ln0w = (const float*)d_in[1];
    const float* ln0b = (const float*)d_in[2];
    const float* ln1w = (const float*)d_in[3];
    const float* ln1b = (const float*)d_in[4];
    const float* qw   = (const float*)d_in[5];
    const float* qb   = (const float*)d_in[6];
    const float* kw   = (const float*)d_in[7];
    const float* kb   = (const float*)d_in[8];
    const float* vw   = (const float*)d_in[9];
    const float* vb   = (const float*)d_in[10];
    const float* w1   = (const float*)d_in[11];
    const float* b1   = (const float*)d_in[12];
    const float* w2   = (const float*)d_in[13];
    const float* b2   = (const float*)d_in[14];
    float* out = (float*)d_out;

    __half *hx, *xnh, *hqw, *hkw, *hvw, *hw1, *hw2, *yh, *h1h, *qh, *kh, *vh;
    float *den, *qkvh, *part, *parth, *partq, *partk;
    cudaGetSymbolAddress((void**)&hx,    g_hx);
    cudaGetSymbolAddress((void**)&xnh,   g_xnh);
    cudaGetSymbolAddress((void**)&hqw,   g_hqw);
    cudaGetSymbolAddress((void**)&hkw,   g_hkw);
    cudaGetSymbolAddress((void**)&hvw,   g_hvw);
    cudaGetSymbolAddress((void**)&hw1,   g_hw1);
    cudaGetSymbolAddress((void**)&hw2,   g_hw2);
    cudaGetSymbolAddress((void**)&yh,    g_yh);
    cudaGetSymbolAddress((void**)&h1h,   g_h1h);
    cudaGetSymbolAddress((void**)&qh,    g_qh);
    cudaGetSymbolAddress((void**)&kh,    g_kh);
    cudaGetSymbolAddress((void**)&vh,    g_vh);
    cudaGetSymbolAddress((void**)&den,   g_den);
    cudaGetSymbolAddress((void**)&qkvh,  g_qkvh);
    cudaGetSymbolAddress((void**)&part,  g_part);
    cudaGetSymbolAddress((void**)&parth, g_parth);
    cudaGetSymbolAddress((void**)&partq, g_partq);
    cudaGetSymbolAddress((void**)&partk, g_partk);

    cudaFuncSetAttribute(hgemm<0,0,3,0,0>, cudaFuncAttributeMaxDynamicSharedMemorySize, HG_SMEM);
    cudaFuncSetAttribute(hgemm<2,1,0,0,1>, cudaFuncAttributeMaxDynamicSharedMemorySize, HG_SMEM);
    cudaFuncSetAttribute(hgemm<0,0,2,0,0>, cudaFuncAttributeMaxDynamicSharedMemorySize, HG_SMEM);
    cudaFuncSetAttribute(attn_kernel, cudaFuncAttributeMaxDynamicSharedMemorySize, ATTN_SMEM);

    // 0+1) fused: fp16-convert weights+x, LN0 -> fp16
    conv_ln0<<<13056, 256>>>(qw, kw, vw, w1, w2, x, ln0w, ln0b,
                             hqw, hkw, hvw, hw1, hw2, hx, xnh);
    // 2) q+k projection partials (fp16 MMA, dual splitK=4)
    hgemm<0,0,3,0,0><<<dim3(AH/128, L/128, 8), 128, HG_SMEM>>>(
        xnh, hqw, nullptr, partq, hkw, partk, L, AH, D/4, D, AH);
    // 2b) q,k = fp16(exp(clip(sum+bias) - 4)), head-major
    reduce_qk<<<dim3(1024, 2), 256>>>(partq, partk, qb, kb, qh, kh);
    // 3) v projection (+bias, head-major, fp16 out)
    hgemm<2,1,0,0,1><<<dim3(DH/128, L/128), 128, HG_SMEM>>>(
        hx, hvw, vb, vh, nullptr, nullptr, L, DH, D, D, DH);
    // 4-6) fused attention (fp16, 512 thr, d-tile 256, 128 CTAs = 1 wave)
    attn_kernel<<<dim3(2, 8, NH), 512, ATTN_SMEM>>>(qh, kh, vh, qkvh, den);
    // 7) y = x + LN1(qkv/den) -> fp16
    y_kernel<<<L, 512>>>(x, qkvh, den, ln1w, ln1b, yh);
    // 8) h1 partials: splitK=2 of y@w1
    hgemm<0,0,2,0,0><<<dim3(FF/128, L/128, 2), 128, HG_SMEM>>>(
        yh, hw1, nullptr, parth, nullptr, nullptr, L, FF, DH/2, DH, FF);
    // 8b) h1 = relu(sum + b1) -> fp16
    reduce_h1<<<2048, 256>>>(parth, b1, h1h);
    // 9) w2 partials: splitK=4
    hgemm<0,0,2,0,0><<<dim3(D/128, L/128, 4), 128, HG_SMEM>>>(
        h1h, hw2, nullptr, part, nullptr, nullptr, L, D, FF/4, FF, D);
    // 10) out = relu(sum+b2)+x
    reduce_out<<<512, 256>>>(part, b2, x, out);
}

// round 12
// speedup vs baseline: 1.1662x; 1.1662x over previous
#include <cuda_runtime.h>
#include <cuda_fp16.h>
#include <math.h>
#include <stdint.h>

#define L  1024
#define D  512
#define NH 8
#define DA 32
#define AH 256
#define DH 4096
#define FF 2048

// -------- scratch --------
__device__ __half g_hx[L * D];
__device__ __half g_xnh[L * D];
__device__ __half g_hqw[D * AH];
__device__ __half g_hkw[D * AH];
__device__ __half g_hvw[D * DH];
__device__ __half g_hw1[DH * FF];
__device__ __half g_hw2[FF * D];
__device__ __half g_yh[(size_t)L * DH];
__device__ __half g_h1h[L * FF];
__device__ __half g_qh[NH * L * DA];
__device__ __half g_kh[NH * L * DA];
__device__ __half g_vh[NH * L * D];
__device__ float g_den[NH * L];
__device__ float g_qkvh[NH * L * D];
__device__ float g_part[4 * L * D];
__device__ float g_parth[2 * L * FF];
__device__ float g_partq[4 * L * AH];
__device__ float g_partk[4 * L * AH];

__device__ __forceinline__ unsigned f2tf32(float v) {
    unsigned o;
    asm volatile("cvt.rna.tf32.f32 %0, %1;" : "=r"(o) : "f"(v));
    return o;
}
__device__ __forceinline__ float rnd(float v) { return __uint_as_float(f2tf32(v)); }

__device__ __forceinline__ void cpa16s(unsigned sa, const void* g) {
    asm volatile("cp.async.cg.shared.global [%0], [%1], 16;\n" :: "r"(sa), "l"(g));
}
#define CP_COMMIT() asm volatile("cp.async.commit_group;\n" ::: "memory")
#define CP_WAIT2()  asm volatile("cp.async.wait_group 2;\n" ::: "memory")

__device__ __forceinline__ void ldsm4(unsigned& r0, unsigned& r1, unsigned& r2, unsigned& r3,
                                      unsigned addr) {
    asm volatile("ldmatrix.sync.aligned.m8n8.x4.shared.b16 {%0,%1,%2,%3}, [%4];"
                 : "=r"(r0), "=r"(r1), "=r"(r2), "=r"(r3) : "r"(addr));
}
__device__ __forceinline__ void ldsm4t(unsigned& r0, unsigned& r1, unsigned& r2, unsigned& r3,
                                       unsigned addr) {
    asm volatile("ldmatrix.sync.aligned.m8n8.x4.trans.shared.b16 {%0,%1,%2,%3}, [%4];"
                 : "=r"(r0), "=r"(r1), "=r"(r2), "=r"(r3) : "r"(addr));
}

#define MMA_F16(c0,c1,c2,c3,a0,a1,a2,a3,b0,b1) \
    asm volatile("mma.sync.aligned.m16n8k16.row.col.f32.f16.f16.f32 " \
        "{%0,%1,%2,%3}, {%4,%5,%6,%7}, {%8,%9}, {%0,%1,%2,%3};" \
        : "+f"(c0), "+f"(c1), "+f"(c2), "+f"(c3) \
        : "r"(a0), "r"(a1), "r"(a2), "r"(a3), "r"(b0), "r"(b1))

__device__ __forceinline__ float2 block_reduce2(float a, float b) {
    __shared__ float2 sh[16];
    int tid = threadIdx.x;
#pragma unroll
    for (int o = 16; o > 0; o >>= 1) {
        a += __shfl_down_sync(0xffffffffu, a, o);
        b += __shfl_down_sync(0xffffffffu, b, o);
    }
    int wid = tid >> 5, lane = tid & 31;
    int nw = blockDim.x >> 5;
    if (lane == 0) sh[wid] = make_float2(a, b);
    __syncthreads();
    if (wid == 0) {
        float2 v = (lane < nw) ? sh[lane] : make_float2(0.f, 0.f);
        a = v.x; b = v.y;
#pragma unroll
        for (int o = 8; o > 0; o >>= 1) {
            a += __shfl_down_sync(0xffffffffu, a, o);
            b += __shfl_down_sync(0xffffffffu, b, o);
        }
        if (lane == 0) sh[0] = make_float2(a, b);
    }
    __syncthreads();
    return sh[0];
}

// -------- fused: fp16 conversion of weights+x AND LN0(x)->fp16 --------
__global__ void conv_ln0(const float* __restrict__ qw, const float* __restrict__ kw,
                         const float* __restrict__ vw, const float* __restrict__ w1,
                         const float* __restrict__ w2, const float* __restrict__ x,
                         const float* __restrict__ ln0w, const float* __restrict__ ln0b,
                         __half* hqw, __half* hkw, __half* hvw, __half* hw1, __half* hw2,
                         __half* hx, __half* xnh)
{
    int t = blockIdx.x;
    int tid = threadIdx.x;
    if (t < 12032) {
        int q = t * 256 + tid;
        const float4* s; __half* d; int off;
        if (q < 32768)        { s = (const float4*)qw; d = hqw; off = q; }
        else if (q < 65536)   { s = (const float4*)kw; d = hkw; off = q - 32768; }
        else if (q < 589824)  { s = (const float4*)vw; d = hvw; off = q - 65536; }
        else if (q < 2686976) { s = (const float4*)w1; d = hw1; off = q - 589824; }
        else if (q < 2949120) { s = (const float4*)w2; d = hw2; off = q - 2686976; }
        else                  { s = (const float4*)x;  d = hx;  off = q - 2949120; }
        float4 v = s[off];
        __half2* d2 = (__half2*)d;
        d2[off * 2]     = __floats2half2_rn(v.x, v.y);
        d2[off * 2 + 1] = __floats2half2_rn(v.z, v.w);
        return;
    }
    int l = t - 12032;
    const float* row = x + (size_t)l * D;
    float v0 = row[tid], v1 = row[tid + 256];
    float2 r = block_reduce2(v0 + v1, v0 * v0 + v1 * v1);
    float mu = r.x * (1.0f / D);
    float var = r.y * (1.0f / D) - mu * mu;
    float rs = rsqrtf(var + 1e-5f);
    xnh[(size_t)l * D + tid]       = __float2half_rn((v0 - mu) * rs * ln0w[tid] + ln0b[tid]);
    xnh[(size_t)l * D + tid + 256] = __float2half_rn((v1 - mu) * rs * ln0w[tid + 256] + ln0b[tid + 256]);
}

// ========== fp16 tensor GEMM: 128x128x32 tiles, 4 warps (64x64), 4 stages ==========
#define HG_ASTR 40
#define HG_BSTR 136
#define HG_ABYT (128 * HG_ASTR * 2)
#define HG_STG  (HG_ABYT + 32 * HG_BSTR * 2)
#define HG_SMEM (4 * HG_STG)
#define PH_STRIDE (128 * 16 + 8)   // padded h-stride (halfs) for permute staging

// EPI: 0 none, 2 +bias, 3 relu(+bias). MODE: 0 plain, 2 splitK, 3 dual-splitK.
// PERM=1 && HOUT=1: smem-staged coalesced head-major fp16 store.
template<int EPI, int PERM, int MODE, int ROUND, int HOUT>
__global__ void __launch_bounds__(128, 2) hgemm(
    const __half* __restrict__ A, const __half* __restrict__ B,
    const float* __restrict__ bias, void* __restrict__ Cv,
    const __half* __restrict__ B2, void* __restrict__ C2v,
    int M, int N, int K, int lda, int ldb)
{
    extern __shared__ char smemc[];
    uint32_t sbase = (uint32_t)__cvta_generic_to_shared(smemc);

    float* C = (float*)Cv;
    int z = blockIdx.z;
    if (MODE == 2) {
        A += (size_t)z * K;
        B += (size_t)z * K * ldb;
        C += (size_t)z * M * N;
    } else if (MODE == 3) {
        int set = z >> 2, zz = z & 3;
        if (set) { B = B2; C = (float*)C2v; }
        A += (size_t)zz * K;
        B += (size_t)zz * K * ldb;
        C += (size_t)zz * M * N;
    }

    int tid = threadIdx.x;
    int wid = tid >> 5, lane = tid & 31;
    int group = lane >> 2, tg = lane & 3;
    int warp_m = wid >> 1, warp_n = wid & 1;
    int m0 = blockIdx.y * 128, n0 = blockIdx.x * 128;
    int kTiles = K / 32;

    const __half* Ab = A + (size_t)(m0 + tid) * lda;
    int br = tid >> 2, bc = (tid & 3) * 32;
    const __half* Bb = B + n0 + bc;

    uint32_t laA = ((lane & 15) * HG_ASTR + ((lane >> 4) << 3)) * 2;
    uint32_t laB = ((lane & 15) * HG_BSTR + ((lane >> 4) << 3)) * 2;
    uint32_t afw = (uint32_t)(warp_m * 64 * HG_ASTR * 2) + laA;
    uint32_t bfw = (uint32_t)(warp_n * 64 * 2) + laB;

    float c[4][8][4];
#pragma unroll
    for (int i = 0; i < 4; i++)
#pragma unroll
        for (int j = 0; j < 8; j++)
#pragma unroll
            for (int r = 0; r < 4; r++) c[i][j][r] = 0.f;

#pragma unroll
    for (int s = 0; s < 3; s++) {
        if (s < kTiles) {
            uint32_t sA = sbase + s * HG_STG;
            uint32_t sB = sA + HG_ABYT;
#pragma unroll
            for (int cc = 0; cc < 4; cc++)
                cpa16s(sA + (tid * HG_ASTR + cc * 8) * 2, Ab + s * 32 + cc * 8);
#pragma unroll
            for (int cc = 0; cc < 4; cc++)
                cpa16s(sB + (br * HG_BSTR + bc + cc * 8) * 2,
                       Bb + (size_t)(s * 32 + br) * ldb + cc * 8);
        }
        CP_COMMIT();
    }
    CP_WAIT2();
    __syncthreads();

    for (int t = 0; t < kTiles; t++) {
        int tp = t + 3;
        if (tp < kTiles) {
            int ps = tp & 3;
            uint32_t sA = sbase + ps * HG_STG;
            uint32_t sB = sA + HG_ABYT;
#pragma unroll
            for (int cc = 0; cc < 4; cc++)
                cpa16s(sA + (tid * HG_ASTR + cc * 8) * 2, Ab + tp * 32 + cc * 8);
#pragma unroll
            for (int cc = 0; cc < 4; cc++)
                cpa16s(sB + (br * HG_BSTR + bc + cc * 8) * 2,
                       Bb + (size_t)(tp * 32 + br) * ldb + cc * 8);
        }
        CP_COMMIT();

        uint32_t aSt = sbase + (t & 3) * HG_STG + afw;
        uint32_t bSt = sbase + (t & 3) * HG_STG + HG_ABYT + bfw;

        unsigned a[2][4][4], b[2][8][2];
#pragma unroll
        for (int kk = 0; kk < 2; kk++) {
#pragma unroll
            for (int mt = 0; mt < 4; mt++)
                ldsm4(a[kk][mt][0], a[kk][mt][1], a[kk][mt][2], a[kk][mt][3],
                      aSt + (unsigned)((mt * 16 * HG_ASTR + kk * 16) * 2));
#pragma unroll
            for (int p = 0; p < 4; p++) {
                unsigned u0, u1, u2, u3;
                ldsm4t(u0, u1, u2, u3,
                       bSt + (unsigned)((p * 16) * 2 + (kk * 16 * HG_BSTR) * 2));
                b[kk][2 * p][0] = u0;     b[kk][2 * p][1] = u1;
                b[kk][2 * p + 1][0] = u2; b[kk][2 * p + 1][1] = u3;
            }
        }
#pragma unroll
        for (int kk = 0; kk < 2; kk++)
#pragma unroll
            for (int mt = 0; mt < 4; mt++)
#pragma unroll
                for (int nt = 0; nt < 8; nt++)
                    MMA_F16(c[mt][nt][0], c[mt][nt][1], c[mt][nt][2], c[mt][nt][3],
                            a[kk][mt][0], a[kk][mt][1], a[kk][mt][2], a[kk][mt][3],
                            b[kk][nt][0], b[kk][nt][1]);

        CP_WAIT2();
        __syncthreads();
    }

    if (PERM == 1 && HOUT == 1) {
        // smem-staged coalesced head-major fp16 store
        __syncthreads();
        __half* st = (__half*)smemc;
#pragma unroll
        for (int mt = 0; mt < 4; mt++) {
#pragma unroll
            for (int nt = 0; nt < 8; nt++) {
#pragma unroll
                for (int r = 0; r < 4; r++) {
                    int row = warp_m * 64 + mt * 16 + group + (r >> 1) * 8;
                    int n = warp_n * 64 + nt * 8 + tg * 2 + (r & 1);
                    float v = c[mt][nt][r];
                    if (EPI == 2) v = v + bias[n0 + n];
                    st[(n & 7) * PH_STRIDE + row * 16 + (n >> 3)] = __float2half_rn(v);
                }
            }
        }
        __syncthreads();
        __half* Ch = (__half*)Cv;
        int NI = N >> 3;   // global inner stride
#pragma unroll
        for (int it = 0; it < 16; it++) {
            int cidx = it * 128 + tid;           // [h(3)][m(7)][chunk(1)]
            int h = cidx >> 8;
            int m = (cidx >> 1) & 127;
            int ck = cidx & 1;
            uint4 v = *(uint4*)&st[h * PH_STRIDE + m * 16 + ck * 8];
            *(uint4*)&Ch[((size_t)(h * M + m0 + m)) * NI + (n0 >> 3) + ck * 8] = v;
        }
        return;
    }

#pragma unroll
    for (int mt = 0; mt < 4; mt++) {
#pragma unroll
        for (int nt = 0; nt < 8; nt++) {
#pragma unroll
            for (int r = 0; r < 4; r++) {
                int m = m0 + warp_m * 64 + mt * 16 + group + (r >> 1) * 8;
                int n = n0 + warp_n * 64 + nt * 8 + tg * 2 + (r & 1);
                float v = c[mt][nt][r];
                if (EPI == 2) v = v + bias[n];
                else if (EPI == 3) v = fmaxf(v + bias[n], 0.f);
                if (ROUND) v = rnd(v);
                C[(size_t)m * N + n] = v;
            }
        }
    }
}

// -------- split-K reduce for q/k: fp16(exp(clip(sum+bias) - 4)), head-major --------
__global__ void reduce_qk(const float* __restrict__ pq, const float* __restrict__ pk,
                          const float* __restrict__ qb, const float* __restrict__ kb,
                          __half* __restrict__ qh, __half* __restrict__ kh)
{
    int set = blockIdx.y;
    const float* p   = set ? pk : pq;
    const float* bia = set ? kb : qb;
    __half* o = set ? kh : qh;
    int i = blockIdx.x * 256 + threadIdx.x;
    int m = i >> 8, n = i & 255;
    float s = p[i] + p[i + 262144] + p[i + 524288] + p[i + 786432] + bia[n];
    s = expf(fminf(fmaxf(s, -10.f), 10.f) - 4.0f);
    int h = n & 7, inner = n >> 3;
    o[((size_t)(h * L + m)) * DA + inner] = __float2half_rn(s);
}

// ================= fused flash attention, fp16, d-tile 128 (R10 known-good) =================
#define AQ_OFF 0
#define AK_OFF 10240
#define AV_OFF 30720
#define AS_OFF 100352
#define ADN_OFF 135168
#define ATTN_SMEM 137216
#define KSTR 40
#define VSTR 136
#define SSTR 136

__global__ void __launch_bounds__(256, 1) attn_kernel(
    const __half* __restrict__ qhp, const __half* __restrict__ khp,
    const __half* __restrict__ vhp, float* __restrict__ qkvh,
    float* __restrict__ den)
{
    extern __shared__ char smc[];
    uint32_t sb = (uint32_t)__cvta_generic_to_shared(smc);
    float* dn = (float*)(smc + ADN_OFF);

    int d0 = blockIdx.x * 128;
    int i  = 7 - blockIdx.y;
    int h  = blockIdx.z;

    int tid = threadIdx.x, lane = tid & 31, wid = tid >> 5;
    int group = lane >> 2, tg = lane & 3;
    int ws_m = wid >> 2, ws_n = wid & 3;

    const __half* Qg = qhp + ((size_t)h * L + i * 128) * DA;
    const __half* Kg = khp + (size_t)h * L * DA;
    const __half* Vg = vhp + (size_t)h * L * D + d0;

    if (tid < 128) { dn[tid] = 0.f; dn[128 + tid] = 0.f; dn[256 + tid] = 0.f; dn[384 + tid] = 0.f; }

    int qr = tid >> 1, qc = (tid & 1) * 16;
    int vr = tid >> 1, vvc = (tid & 1) * 64;

    cpa16s(sb + AQ_OFF + (qr * KSTR + qc) * 2,     Qg + qr * DA + qc);
    cpa16s(sb + AQ_OFF + (qr * KSTR + qc + 8) * 2, Qg + qr * DA + qc + 8);
    CP_COMMIT();
    cpa16s(sb + AK_OFF + (qr * KSTR + qc) * 2,     Kg + qr * DA + qc);
    cpa16s(sb + AK_OFF + (qr * KSTR + qc + 8) * 2, Kg + qr * DA + qc + 8);
#pragma unroll
    for (int kk = 0; kk < 8; kk++)
        cpa16s(sb + AV_OFF + (vr * VSTR + vvc + kk * 8) * 2, Vg + (size_t)vr * D + vvc + kk * 8);
    CP_COMMIT();

    float oc[4][4][4];
#pragma unroll
    for (int a = 0; a < 4; a++)
#pragma unroll
        for (int b = 0; b < 4; b++)
#pragma unroll
            for (int r = 0; r < 4; r++) oc[a][b][r] = 0.f;
    float dpart[8];
#pragma unroll
    for (int a = 0; a < 8; a++) dpart[a] = 0.f;

    uint32_t laK = ((lane & 15) * KSTR + ((lane >> 4) << 3)) * 2;
    uint32_t laV = ((lane & 15) * VSTR + ((lane >> 4) << 3)) * 2;
    uint32_t qfb = sb + AQ_OFF + (uint32_t)(ws_m * 64 * KSTR * 2) + laK;
    uint32_t sfb = sb + AS_OFF + (uint32_t)(ws_m * 64 * SSTR * 2)
                 + ((lane & 15) * SSTR + ((lane >> 4) << 3)) * 2;

    for (int j = 0; j <= i; j++) {
        int buf = j & 1;
        if (j < i) {
            int nb = buf ^ 1;
            const __half* kg = Kg + (size_t)(j + 1) * 128 * DA;
            const __half* vg = Vg + (size_t)(j + 1) * 128 * D;
            cpa16s(sb + AK_OFF + nb * 10240 + (qr * KSTR + qc) * 2,     kg + qr * DA + qc);
            cpa16s(sb + AK_OFF + nb * 10240 + (qr * KSTR + qc + 8) * 2, kg + qr * DA + qc + 8);
#pragma unroll
            for (int kk = 0; kk < 8; kk++)
                cpa16s(sb + AV_OFF + nb * 34816 + (vr * VSTR + vvc + kk * 8) * 2,
                       vg + (size_t)vr * D + vvc + kk * 8);
            CP_COMMIT();
            asm volatile("cp.async.wait_group 1;\n" ::: "memory");
        } else {
            asm volatile("cp.async.wait_group 0;\n" ::: "memory");
        }
        __syncthreads();

        float sc[4][4][4];
#pragma unroll
        for (int a = 0; a < 4; a++)
#pragma unroll
            for (int b = 0; b < 4; b++)
#pragma unroll
                for (int r = 0; r < 4; r++) sc[a][b][r] = 0.f;

        uint32_t kb0 = sb + AK_OFF + (uint32_t)(buf * 10240)
                     + (uint32_t)(ws_n * 32 * KSTR * 2) + laK;
#pragma unroll
        for (int kc = 0; kc < 2; kc++) {
            unsigned qa[4][4], kb[4][2];
#pragma unroll
            for (int mt = 0; mt < 4; mt++)
                ldsm4(qa[mt][0], qa[mt][1], qa[mt][2], qa[mt][3],
                      qfb + (unsigned)((mt * 16 * KSTR + kc * 16) * 2));
#pragma unroll
            for (int p = 0; p < 2; p++) {
                unsigned u0, u1, u2, u3;
                ldsm4(u0, u1, u2, u3, kb0 + (unsigned)((p * 16 * KSTR + kc * 16) * 2));
                kb[2 * p][0] = u0;     kb[2 * p][1] = u2;
                kb[2 * p + 1][0] = u1; kb[2 * p + 1][1] = u3;
            }
#pragma unroll
            for (int mt = 0; mt < 4; mt++)
#pragma unroll
                for (int nt = 0; nt < 4; nt++)
                    MMA_F16(sc[mt][nt][0], sc[mt][nt][1], sc[mt][nt][2], sc[mt][nt][3],
                            qa[mt][0], qa[mt][1], qa[mt][2], qa[mt][3],
                            kb[nt][0], kb[nt][1]);
        }

        bool diag = (j == i);
#pragma unroll
        for (int mt = 0; mt < 4; mt++) {
#pragma unroll
            for (int rp = 0; rp < 2; rp++) {
                int row = ws_m * 64 + mt * 16 + group + rp * 8;
#pragma unroll
                for (int nt = 0; nt < 4; nt++) {
                    int colb = ws_n * 32 + nt * 8 + tg * 2;
                    float v0 = sc[mt][nt][rp * 2], v1 = sc[mt][nt][rp * 2 + 1];
                    if (diag) {
                        if (colb > row) v0 = 0.f;
                        if (colb + 1 > row) v1 = 0.f;
                    }
                    __half2 hv = __floats2half2_rn(v0, v1);
                    float2 fb = __half22float2(hv);
                    dpart[mt * 2 + rp] += fb.x + fb.y;
                    *(__half2*)(smc + AS_OFF + ((size_t)row * SSTR + colb) * 2) = hv;
                }
            }
        }
        __syncthreads();

        uint32_t vb0 = sb + AV_OFF + (uint32_t)(buf * 34816)
                     + (uint32_t)(ws_n * 32 * 2) + laV;
#pragma unroll
        for (int kc = 0; kc < 8; kc++) {
            unsigned sa[4][4], vb[4][2];
#pragma unroll
            for (int mt = 0; mt < 4; mt++)
                ldsm4(sa[mt][0], sa[mt][1], sa[mt][2], sa[mt][3],
                      sfb + (unsigned)((mt * 16 * SSTR + kc * 16) * 2));
#pragma unroll
            for (int p = 0; p < 2; p++) {
                unsigned u0, u1, u2, u3;
                ldsm4t(u0, u1, u2, u3,
                       vb0 + (unsigned)((kc * 16 * VSTR + p * 16) * 2));
                vb[2 * p][0] = u0;     vb[2 * p][1] = u1;
                vb[2 * p + 1][0] = u2; vb[2 * p + 1][1] = u3;
            }
#pragma unroll
            for (int mt = 0; mt < 4; mt++)
#pragma unroll
                for (int nt = 0; nt < 4; nt++)
                    MMA_F16(oc[mt][nt][0], oc[mt][nt][1], oc[mt][nt][2], oc[mt][nt][3],
                            sa[mt][0], sa[mt][1], sa[mt][2], sa[mt][3],
                            vb[nt][0], vb[nt][1]);
        }
        __syncthreads();
    }

#pragma unroll
    for (int mt = 0; mt < 4; mt++)
#pragma unroll
        for (int rp = 0; rp < 2; rp++) {
            int m = i * 128 + ws_m * 64 + mt * 16 + group + rp * 8;
#pragma unroll
            for (int nt = 0; nt < 4; nt++) {
                int dd = d0 + ws_n * 32 + nt * 8 + tg * 2;
                *(float2*)&qkvh[((size_t)h * L + m) * D + dd] =
                    make_float2(oc[mt][nt][rp * 2], oc[mt][nt][rp * 2 + 1]);
            }
        }

#pragma unroll
    for (int q = 0; q < 8; q++) {
        float v = dpart[q];
        v += __shfl_xor_sync(0xffffffffu, v, 1, 4);
        v += __shfl_xor_sync(0xffffffffu, v, 2, 4);
        dpart[q] = v;
    }
    if (tg == 0) {
#pragma unroll
        for (int mt = 0; mt < 4; mt++)
#pragma unroll
            for (int rp = 0; rp < 2; rp++) {
                int row = ws_m * 64 + mt * 16 + group + rp * 8;
                dn[ws_n * 128 + row] = dpart[mt * 2 + rp];
            }
    }
    __syncthreads();
    if (blockIdx.x == 0 && tid < 128)
        den[h * L + i * 128 + tid] = dn[tid] + dn[128 + tid] + dn[256 + tid] + dn[384 + tid];
}

// -------- y = x + LN1(qkv/den), fp16 output --------
__global__ void y_kernel(const float* __restrict__ x, const float* __restrict__ qkvh,
                         const float* __restrict__ den, const float* __restrict__ w,
                         const float* __restrict__ b, __half* __restrict__ y)
{
    int l = blockIdx.x, tid = threadIdx.x;
    float t[8];
    float s = 0.f, s2 = 0.f;
#pragma unroll
    for (int r = 0; r < 8; r++) {
        int j = tid + r * 512;
        int h = j & 7, d = j >> 3;
        float v = qkvh[((size_t)(h * L + l)) * D + d] / den[h * L + l];
        t[r] = v; s += v; s2 += v * v;
    }
    float2 red = block_reduce2(s, s2);
    float mu = red.x * (1.0f / DH);
    float rs = rsqrtf(red.y * (1.0f / DH) - mu * mu + 1e-5f);
#pragma unroll
    for (int r = 0; r < 8; r++) {
        int j = tid + r * 512;
        y[(size_t)l * DH + j] =
            __float2half_rn(x[(size_t)l * D + (j >> 3)] + (t[r] - mu) * rs * w[j] + b[j]);
    }
}

__global__ void reduce_h1(const float* __restrict__ part, const float* __restrict__ b1,
                          __half* __restrict__ h1)
{
    int q = blockIdx.x * 256 + threadIdx.x;
    const float4* p = (const float4*)part;
    float4 v0 = p[q];
    float4 v1 = p[q + (L * FF / 4)];
    float4 bb = ((const float4*)b1)[q & (FF / 4 - 1)];
    __half2* H = (__half2*)h1;
    H[q * 2]     = __floats2half2_rn(fmaxf(v0.x + v1.x + bb.x, 0.f),
                                     fmaxf(v0.y + v1.y + bb.y, 0.f));
    H[q * 2 + 1] = __floats2half2_rn(fmaxf(v0.z + v1.z + bb.z, 0.f),
                                     fmaxf(v0.w + v1.w + bb.w, 0.f));
}

__global__ void reduce_out(const float* __restrict__ part, const float* __restrict__ b2,
                           const float* __restrict__ x, float* __restrict__ out)
{
    int q = blockIdx.x * 256 + threadIdx.x;
    const float4* p = (const float4*)part;
    float4 v0 = p[q];
    float4 v1 = p[q + 131072];
    float4 v2 = p[q + 262144];
    float4 v3 = p[q + 393216];
    float4 bb = ((const float4*)b2)[q & 127];
    float4 xx = ((const float4*)x)[q];
    float4 o;
    o.x = fmaxf(v0.x + v1.x + v2.x + v3.x + bb.x, 0.f) + xx.x;
    o.y = fmaxf(v0.y + v1.y + v2.y + v3.y + bb.y, 0.f) + xx.y;
    o.z = fmaxf(v0.z + v1.z + v2.z + v3.z + bb.z, 0.f) + xx.z;
    o.w = fmaxf(v0.w + v1.w + v2.w + v3.w + bb.w, 0.f) + xx.w;
    ((float4*)out)[q] = o;
}

extern "C" void kernel_launch(void* const* d_in, const int* in_sizes, int n_in,
                              void* d_out, int out_size)
{
    const float* x    = (const float*)d_in[0];
    const float* ln0w = (const float*)d_in[1];
    const float* ln0b = (const float*)d_in[2];
    const float* ln1w = (const float*)d_in[3];
    const float* ln1b = (const float*)d_in[4];
    const float* qw   = (const float*)d_in[5];
    const float* qb   = (const float*)d_in[6];
    const float* kw   = (const float*)d_in[7];
    const float* kb   = (const float*)d_in[8];
    const float* vw   = (const float*)d_in[9];
    const float* vb   = (const float*)d_in[10];
    const float* w1   = (const float*)d_in[11];
    const float* b1   = (const float*)d_in[12];
    const float* w2   = (const float*)d_in[13];
    const float* b2   = (const float*)d_in[14];
    float* out = (float*)d_out;

    __half *hx, *xnh, *hqw, *hkw, *hvw, *hw1, *hw2, *yh, *h1h, *qh, *kh, *vh;
    float *den, *qkvh, *part, *parth, *partq, *partk;
    cudaGetSymbolAddress((void**)&hx,    g_hx);
    cudaGetSymbolAddress((void**)&xnh,   g_xnh);
    cudaGetSymbolAddress((void**)&hqw,   g_hqw);
    cudaGetSymbolAddress((void**)&hkw,   g_hkw);
    cudaGetSymbolAddress((void**)&hvw,   g_hvw);
    cudaGetSymbolAddress((void**)&hw1,   g_hw1);
    cudaGetSymbolAddress((void**)&hw2,   g_hw2);
    cudaGetSymbolAddress((void**)&yh,    g_yh);
    cudaGetSymbolAddress((void**)&h1h,   g_h1h);
    cudaGetSymbolAddress((void**)&qh,    g_qh);
    cudaGetSymbolAddress((void**)&kh,    g_kh);
    cudaGetSymbolAddress((void**)&vh,    g_vh);
    cudaGetSymbolAddress((void**)&den,   g_den);
    cudaGetSymbolAddress((void**)&qkvh,  g_qkvh);
    cudaGetSymbolAddress((void**)&part,  g_part);
    cudaGetSymbolAddress((void**)&parth, g_parth);
    cudaGetSymbolAddress((void**)&partq, g_partq);
    cudaGetSymbolAddress((void**)&partk, g_partk);

    cudaFuncSetAttribute(hgemm<0,0,3,0,0>, cudaFuncAttributeMaxDynamicSharedMemorySize, HG_SMEM);
    cudaFuncSetAttribute(hgemm<2,1,0,0,1>, cudaFuncAttributeMaxDynamicSharedMemorySize, HG_SMEM);
    cudaFuncSetAttribute(hgemm<0,0,2,0,0>, cudaFuncAttributeMaxDynamicSharedMemorySize, HG_SMEM);
    cudaFuncSetAttribute(attn_kernel, cudaFuncAttributeMaxDynamicSharedMemorySize, ATTN_SMEM);

    // 0+1) fused: fp16-convert weights+x, LN0 -> fp16
    conv_ln0<<<13056, 256>>>(qw, kw, vw, w1, w2, x, ln0w, ln0b,
                             hqw, hkw, hvw, hw1, hw2, hx, xnh);
    // 2) q+k projection partials (fp16 MMA, dual splitK=4)
    hgemm<0,0,3,0,0><<<dim3(AH/128, L/128, 8), 128, HG_SMEM>>>(
        xnh, hqw, nullptr, partq, hkw, partk, L, AH, D/4, D, AH);
    // 2b) q,k = fp16(exp(clip(sum+bias) - 4)), head-major
    reduce_qk<<<dim3(1024, 2), 256>>>(partq, partk, qb, kb, qh, kh);
    // 3) v projection (+bias, head-major, fp16 out, smem-staged coalesced store)
    hgemm<2,1,0,0,1><<<dim3(DH/128, L/128), 128, HG_SMEM>>>(
        hx, hvw, vb, vh, nullptr, nullptr, L, DH, D, D, DH);
    // 4-6) fused attention (fp16, d-tile 128, R10 config)
    attn_kernel<<<dim3(4, 8, NH), 256, ATTN_SMEM>>>(qh, kh, vh, qkvh, den);
    // 7) y = x + LN1(qkv/den) -> fp16
    y_kernel<<<L, 512>>>(x, qkvh, den, ln1w, ln1b, yh);
    // 8) h1 partials: splitK=2 of y@w1
    hgemm<0,0,2,0,0><<<dim3(FF/128, L/128, 2), 128, HG_SMEM>>>(
        yh, hw1, nullptr, parth, nullptr, nullptr, L, FF, DH/2, DH, FF);
    // 8b) h1 = relu(sum + b1) -> fp16
    reduce_h1<<<2048, 256>>>(parth, b1, h1h);
    // 9) w2 partials: splitK=4
    hgemm<0,0,2,0,0><<<dim3(D/128, L/128, 4), 128, HG_SMEM>>>(
        h1h, hw2, nullptr, part, nullptr, nullptr, L, D, FF/4, FF, D);
    // 10) out = relu(sum+b2)+x
    reduce_out<<<512, 256>>>(part, b2, x, out);
}

// round 13
// speedup vs baseline: 1.1883x; 1.0190x over previous
#include <cuda_runtime.h>
#include <cuda_fp16.h>
#include <math.h>
#include <stdint.h>

#define L  1024
#define D  512
#define NH 8
#define DA 32
#define AH 256
#define DH 4096
#define FF 2048

// -------- scratch --------
__device__ __half g_hx[L * D];
__device__ __half g_xnh[L * D];
__device__ __half g_hqw[D * AH];
__device__ __half g_hkw[D * AH];
__device__ __half g_hvw[D * DH];
__device__ __half g_hw1[DH * FF];
__device__ __half g_hw2[FF * D];
__device__ __half g_yh[(size_t)L * DH];
__device__ __half g_h1h[L * FF];
__device__ __half g_qh[NH * L * DA];
__device__ __half g_kh[NH * L * DA];
__device__ __half g_vh[NH * L * D];
__device__ float g_den[NH * L];
__device__ float g_qkvh[NH * L * D];
__device__ float g_part[4 * L * D];
__device__ float g_parth[2 * L * FF];
__device__ float g_partq[4 * L * AH];
__device__ float g_partk[4 * L * AH];

__device__ __forceinline__ void cpa16s(unsigned sa, const void* g) {
    asm volatile("cp.async.cg.shared.global [%0], [%1], 16;\n" :: "r"(sa), "l"(g));
}
#define CP_COMMIT() asm volatile("cp.async.commit_group;\n" ::: "memory")
#define CP_WAIT2()  asm volatile("cp.async.wait_group 2;\n" ::: "memory")

__device__ __forceinline__ void ldsm4(unsigned& r0, unsigned& r1, unsigned& r2, unsigned& r3,
                                      unsigned addr) {
    asm volatile("ldmatrix.sync.aligned.m8n8.x4.shared.b16 {%0,%1,%2,%3}, [%4];"
                 : "=r"(r0), "=r"(r1), "=r"(r2), "=r"(r3) : "r"(addr));
}
__device__ __forceinline__ void ldsm4t(unsigned& r0, unsigned& r1, unsigned& r2, unsigned& r3,
                                       unsigned addr) {
    asm volatile("ldmatrix.sync.aligned.m8n8.x4.trans.shared.b16 {%0,%1,%2,%3}, [%4];"
                 : "=r"(r0), "=r"(r1), "=r"(r2), "=r"(r3) : "r"(addr));
}

#define MMA_F16(c0,c1,c2,c3,a0,a1,a2,a3,b0,b1) \
    asm volatile("mma.sync.aligned.m16n8k16.row.col.f32.f16.f16.f32 " \
        "{%0,%1,%2,%3}, {%4,%5,%6,%7}, {%8,%9}, {%0,%1,%2,%3};" \
        : "+f"(c0), "+f"(c1), "+f"(c2), "+f"(c3) \
        : "r"(a0), "r"(a1), "r"(a2), "r"(a3), "r"(b0), "r"(b1))

__device__ __forceinline__ float2 block_reduce2(float a, float b) {
    __shared__ float2 sh[16];
    int tid = threadIdx.x;
#pragma unroll
    for (int o = 16; o > 0; o >>= 1) {
        a += __shfl_down_sync(0xffffffffu, a, o);
        b += __shfl_down_sync(0xffffffffu, b, o);
    }
    int wid = tid >> 5, lane = tid & 31;
    int nw = blockDim.x >> 5;
    if (lane == 0) sh[wid] = make_float2(a, b);
    __syncthreads();
    if (wid == 0) {
        float2 v = (lane < nw) ? sh[lane] : make_float2(0.f, 0.f);
        a = v.x; b = v.y;
#pragma unroll
        for (int o = 8; o > 0; o >>= 1) {
            a += __shfl_down_sync(0xffffffffu, a, o);
            b += __shfl_down_sync(0xffffffffu, b, o);
        }
        if (lane == 0) sh[0] = make_float2(a, b);
    }
    __syncthreads();
    return sh[0];
}

// -------- fused: fp16 conversion of weights+x AND LN0(x)->fp16 --------
__global__ void conv_ln0(const float* __restrict__ qw, const float* __restrict__ kw,
                         const float* __restrict__ vw, const float* __restrict__ w1,
                         const float* __restrict__ w2, const float* __restrict__ x,
                         const float* __restrict__ ln0w, const float* __restrict__ ln0b,
                         __half* hqw, __half* hkw, __half* hvw, __half* hw1, __half* hw2,
                         __half* hx, __half* xnh)
{
    int t = blockIdx.x;
    int tid = threadIdx.x;
    if (t < 12032) {
        int q = t * 256 + tid;
        const float4* s; __half* d; int off;
        if (q < 32768)        { s = (const float4*)qw; d = hqw; off = q; }
        else if (q < 65536)   { s = (const float4*)kw; d = hkw; off = q - 32768; }
        else if (q < 589824)  { s = (const float4*)vw; d = hvw; off = q - 65536; }
        else if (q < 2686976) { s = (const float4*)w1; d = hw1; off = q - 589824; }
        else if (q < 2949120) { s = (const float4*)w2; d = hw2; off = q - 2686976; }
        else                  { s = (const float4*)x;  d = hx;  off = q - 2949120; }
        float4 v = s[off];
        __half2* d2 = (__half2*)d;
        d2[off * 2]     = __floats2half2_rn(v.x, v.y);
        d2[off * 2 + 1] = __floats2half2_rn(v.z, v.w);
        return;
    }
    int l = t - 12032;
    const float* row = x + (size_t)l * D;
    float v0 = row[tid], v1 = row[tid + 256];
    float2 r = block_reduce2(v0 + v1, v0 * v0 + v1 * v1);
    float mu = r.x * (1.0f / D);
    float var = r.y * (1.0f / D) - mu * mu;
    float rs = rsqrtf(var + 1e-5f);
    xnh[(size_t)l * D + tid]       = __float2half_rn((v0 - mu) * rs * ln0w[tid] + ln0b[tid]);
    xnh[(size_t)l * D + tid + 256] = __float2half_rn((v1 - mu) * rs * ln0w[tid + 256] + ln0b[tid + 256]);
}

// ========== fp16 tensor GEMM mainloop (device fn): 128x128x32 tiles, 4 warps ==========
#define HG_ASTR 40
#define HG_BSTR 136
#define HG_ABYT (128 * HG_ASTR * 2)
#define HG_STG  (HG_ABYT + 32 * HG_BSTR * 2)
#define HG_SMEM (4 * HG_STG)
#define PH_STRIDE (128 * 16 + 8)

__device__ __forceinline__ void hg_main(
    uint32_t sbase, const __half* __restrict__ A, const __half* __restrict__ B,
    int N, int K, int lda, int ldb, int m0, int n0, float (&c)[4][8][4])
{
    int tid = threadIdx.x;
    int wid = tid >> 5, lane = tid & 31;
    int warp_m = wid >> 1, warp_n = wid & 1;
    int kTiles = K / 32;

    const __half* Ab = A + (size_t)(m0 + tid) * lda;
    int br = tid >> 2, bc = (tid & 3) * 32;
    const __half* Bb = B + n0 + bc;

    uint32_t laA = ((lane & 15) * HG_ASTR + ((lane >> 4) << 3)) * 2;
    uint32_t laB = ((lane & 15) * HG_BSTR + ((lane >> 4) << 3)) * 2;
    uint32_t afw = (uint32_t)(warp_m * 64 * HG_ASTR * 2) + laA;
    uint32_t bfw = (uint32_t)(warp_n * 64 * 2) + laB;

#pragma unroll
    for (int i = 0; i < 4; i++)
#pragma unroll
        for (int j = 0; j < 8; j++)
#pragma unroll
            for (int r = 0; r < 4; r++) c[i][j][r] = 0.f;

#pragma unroll
    for (int s = 0; s < 3; s++) {
        if (s < kTiles) {
            uint32_t sA = sbase + s * HG_STG;
            uint32_t sB = sA + HG_ABYT;
#pragma unroll
            for (int cc = 0; cc < 4; cc++)
                cpa16s(sA + (tid * HG_ASTR + cc * 8) * 2, Ab + s * 32 + cc * 8);
#pragma unroll
            for (int cc = 0; cc < 4; cc++)
                cpa16s(sB + (br * HG_BSTR + bc + cc * 8) * 2,
                       Bb + (size_t)(s * 32 + br) * ldb + cc * 8);
        }
        CP_COMMIT();
    }
    CP_WAIT2();
    __syncthreads();

    for (int t = 0; t < kTiles; t++) {
        int tp = t + 3;
        if (tp < kTiles) {
            int ps = tp & 3;
            uint32_t sA = sbase + ps * HG_STG;
            uint32_t sB = sA + HG_ABYT;
#pragma unroll
            for (int cc = 0; cc < 4; cc++)
                cpa16s(sA + (tid * HG_ASTR + cc * 8) * 2, Ab + tp * 32 + cc * 8);
#pragma unroll
            for (int cc = 0; cc < 4; cc++)
                cpa16s(sB + (br * HG_BSTR + bc + cc * 8) * 2,
                       Bb + (size_t)(tp * 32 + br) * ldb + cc * 8);
        }
        CP_COMMIT();

        uint32_t aSt = sbase + (t & 3) * HG_STG + afw;
        uint32_t bSt = sbase + (t & 3) * HG_STG + HG_ABYT + bfw;

        unsigned a[2][4][4], b[2][8][2];
#pragma unroll
        for (int kk = 0; kk < 2; kk++) {
#pragma unroll
            for (int mt = 0; mt < 4; mt++)
                ldsm4(a[kk][mt][0], a[kk][mt][1], a[kk][mt][2], a[kk][mt][3],
                      aSt + (unsigned)((mt * 16 * HG_ASTR + kk * 16) * 2));
#pragma unroll
            for (int p = 0; p < 4; p++) {
                unsigned u0, u1, u2, u3;
                ldsm4t(u0, u1, u2, u3,
                       bSt + (unsigned)((p * 16) * 2 + (kk * 16 * HG_BSTR) * 2));
                b[kk][2 * p][0] = u0;     b[kk][2 * p][1] = u1;
                b[kk][2 * p + 1][0] = u2; b[kk][2 * p + 1][1] = u3;
            }
        }
#pragma unroll
        for (int kk = 0; kk < 2; kk++)
#pragma unroll
            for (int mt = 0; mt < 4; mt++)
#pragma unroll
                for (int nt = 0; nt < 8; nt++)
                    MMA_F16(c[mt][nt][0], c[mt][nt][1], c[mt][nt][2], c[mt][nt][3],
                            a[kk][mt][0], a[kk][mt][1], a[kk][mt][2], a[kk][mt][3],
                            b[kk][nt][0], b[kk][nt][1]);

        CP_WAIT2();
        __syncthreads();
    }
}

// ---- epilogue: plain fp32 store (optional bias/relu) ----
template<int EPI>
__device__ __forceinline__ void epi_plain(
    float (&c)[4][8][4], const float* __restrict__ bias,
    float* __restrict__ C, int N, int m0, int n0)
{
    int tid = threadIdx.x;
    int wid = tid >> 5, lane = tid & 31;
    int group = lane >> 2, tg = lane & 3;
    int warp_m = wid >> 1, warp_n = wid & 1;
#pragma unroll
    for (int mt = 0; mt < 4; mt++)
#pragma unroll
        for (int nt = 0; nt < 8; nt++)
#pragma unroll
            for (int r = 0; r < 4; r++) {
                int m = m0 + warp_m * 64 + mt * 16 + group + (r >> 1) * 8;
                int n = n0 + warp_n * 64 + nt * 8 + tg * 2 + (r & 1);
                float v = c[mt][nt][r];
                if (EPI == 2) v = v + bias[n];
                else if (EPI == 3) v = fmaxf(v + bias[n], 0.f);
                C[(size_t)m * N + n] = v;
            }
}

// ---- epilogue: smem-staged coalesced head-major fp16 store (+bias) ----
__device__ __forceinline__ void epi_perm_half(
    float (&c)[4][8][4], char* smemc, const float* __restrict__ bias,
    __half* __restrict__ Ch, int M, int N, int m0, int n0)
{
    int tid = threadIdx.x;
    int wid = tid >> 5, lane = tid & 31;
    int group = lane >> 2, tg = lane & 3;
    int warp_m = wid >> 1, warp_n = wid & 1;
    __syncthreads();
    __half* st = (__half*)smemc;
#pragma unroll
    for (int mt = 0; mt < 4; mt++)
#pragma unroll
        for (int nt = 0; nt < 8; nt++)
#pragma unroll
            for (int r = 0; r < 4; r++) {
                int row = warp_m * 64 + mt * 16 + group + (r >> 1) * 8;
                int n = warp_n * 64 + nt * 8 + tg * 2 + (r & 1);
                float v = c[mt][nt][r] + bias[n0 + n];
                st[(n & 7) * PH_STRIDE + row * 16 + (n >> 3)] = __float2half_rn(v);
            }
    __syncthreads();
    int NI = N >> 3;
#pragma unroll
    for (int it = 0; it < 16; it++) {
        int cidx = it * 128 + tid;
        int h = cidx >> 8;
        int m = (cidx >> 1) & 127;
        int ck = cidx & 1;
        uint4 v = *(uint4*)&st[h * PH_STRIDE + m * 16 + ck * 8];
        *(uint4*)&Ch[((size_t)(h * M + m0 + m)) * NI + (n0 >> 3) + ck * 8] = v;
    }
}

// ========== fused projection launch: z=1 -> v-proj, z=0 -> q/k dual-splitK ==========
__global__ void __launch_bounds__(128, 2) fused_proj(
    const __half* __restrict__ hx, const __half* __restrict__ hvw,
    const float* __restrict__ vb, __half* __restrict__ vh,
    const __half* __restrict__ xnh, const __half* __restrict__ hqw,
    const __half* __restrict__ hkw, float* __restrict__ partq,
    float* __restrict__ partk)
{
    extern __shared__ char smemc[];
    uint32_t sbase = (uint32_t)__cvta_generic_to_shared(smemc);
    float c[4][8][4];
    int m0 = blockIdx.y * 128;

    if (blockIdx.z == 1) {
        int n0 = blockIdx.x * 128;
        hg_main(sbase, hx, hvw, DH, D, D, DH, m0, n0, c);
        epi_perm_half(c, smemc, vb, vh, L, DH, m0, n0);
    } else {
        int bx = blockIdx.x;
        if (bx >= 16) return;      // before any barrier/cp.async
        int xt = bx & 1, ks = (bx >> 1) & 3, set = bx >> 3;
        const __half* A = xnh + ks * 128;                         // column slice of K
        const __half* B = (set ? hkw : hqw) + (size_t)ks * 128 * AH;
        float* C = (set ? partk : partq) + (size_t)ks * L * AH;
        int n0 = xt * 128;
        hg_main(sbase, A, B, AH, 128, D, AH, m0, n0, c);
        epi_plain<0>(c, nullptr, C, AH, m0, n0);
    }
}

// ========== standalone hgemm for FFN (splitK fp32-out) ==========
template<int MODE>
__global__ void __launch_bounds__(128, 2) hgemm(
    const __half* __restrict__ A, const __half* __restrict__ B,
    float* __restrict__ C, int M, int N, int K, int lda, int ldb)
{
    extern __shared__ char smemc[];
    uint32_t sbase = (uint32_t)__cvta_generic_to_shared(smemc);
    int z = blockIdx.z;
    if (MODE == 2) {
        A += (size_t)z * K;
        B += (size_t)z * K * ldb;
        C += (size_t)z * M * N;
    }
    float c[4][8][4];
    int m0 = blockIdx.y * 128, n0 = blockIdx.x * 128;
    hg_main(sbase, A, B, N, K, lda, ldb, m0, n0, c);
    epi_plain<0>(c, nullptr, C, N, m0, n0);
}

// -------- split-K reduce for q/k: fp16(exp(clip(sum+bias) - 4)), head-major --------
__global__ void reduce_qk(const float* __restrict__ pq, const float* __restrict__ pk,
                          const float* __restrict__ qb, const float* __restrict__ kb,
                          __half* __restrict__ qh, __half* __restrict__ kh)
{
    int set = blockIdx.y;
    const float* p   = set ? pk : pq;
    const float* bia = set ? kb : qb;
    __half* o = set ? kh : qh;
    int i = blockIdx.x * 256 + threadIdx.x;
    int m = i >> 8, n = i & 255;
    float s = p[i] + p[i + 262144] + p[i + 524288] + p[i + 786432] + bia[n];
    s = expf(fminf(fmaxf(s, -10.f), 10.f) - 4.0f);
    int h = n & 7, inner = n >> 3;
    o[((size_t)(h * L + m)) * DA + inner] = __float2half_rn(s);
}

// ================= fused flash attention, fp16, d-tile 128 (R10 known-good) =================
#define AQ_OFF 0
#define AK_OFF 10240
#define AV_OFF 30720
#define AS_OFF 100352
#define ADN_OFF 135168
#define ATTN_SMEM 137216
#define KSTR 40
#define VSTR 136
#define SSTR 136

__global__ void __launch_bounds__(256, 1) attn_kernel(
    const __half* __restrict__ qhp, const __half* __restrict__ khp,
    const __half* __restrict__ vhp, float* __restrict__ qkvh,
    float* __restrict__ den)
{
    extern __shared__ char smc[];
    uint32_t sb = (uint32_t)__cvta_generic_to_shared(smc);
    float* dn = (float*)(smc + ADN_OFF);

    int d0 = blockIdx.x * 128;
    int i  = 7 - blockIdx.y;
    int h  = blockIdx.z;

    int tid = threadIdx.x, lane = tid & 31, wid = tid >> 5;
    int group = lane >> 2, tg = lane & 3;
    int ws_m = wid >> 2, ws_n = wid & 3;

    const __half* Qg = qhp + ((size_t)h * L + i * 128) * DA;
    const __half* Kg = khp + (size_t)h * L * DA;
    const __half* Vg = vhp + (size_t)h * L * D + d0;

    if (tid < 128) { dn[tid] = 0.f; dn[128 + tid] = 0.f; dn[256 + tid] = 0.f; dn[384 + tid] = 0.f; }

    int qr = tid >> 1, qc = (tid & 1) * 16;
    int vr = tid >> 1, vvc = (tid & 1) * 64;

    cpa16s(sb + AQ_OFF + (qr * KSTR + qc) * 2,     Qg + qr * DA + qc);
    cpa16s(sb + AQ_OFF + (qr * KSTR + qc + 8) * 2, Qg + qr * DA + qc + 8);
    CP_COMMIT();
    cpa16s(sb + AK_OFF + (qr * KSTR + qc) * 2,     Kg + qr * DA + qc);
    cpa16s(sb + AK_OFF + (qr * KSTR + qc + 8) * 2, Kg + qr * DA + qc + 8);
#pragma unroll
    for (int kk = 0; kk < 8; kk++)
        cpa16s(sb + AV_OFF + (vr * VSTR + vvc + kk * 8) * 2, Vg + (size_t)vr * D + vvc + kk * 8);
    CP_COMMIT();

    float oc[4][4][4];
#pragma unroll
    for (int a = 0; a < 4; a++)
#pragma unroll
        for (int b = 0; b < 4; b++)
#pragma unroll
            for (int r = 0; r < 4; r++) oc[a][b][r] = 0.f;
    float dpart[8];
#pragma unroll
    for (int a = 0; a < 8; a++) dpart[a] = 0.f;

    uint32_t laK = ((lane & 15) * KSTR + ((lane >> 4) << 3)) * 2;
    uint32_t laV = ((lane & 15) * VSTR + ((lane >> 4) << 3)) * 2;
    uint32_t qfb = sb + AQ_OFF + (uint32_t)(ws_m * 64 * KSTR * 2) + laK;
    uint32_t sfb = sb + AS_OFF + (uint32_t)(ws_m * 64 * SSTR * 2)
                 + ((lane & 15) * SSTR + ((lane >> 4) << 3)) * 2;

    for (int j = 0; j <= i; j++) {
        int buf = j & 1;
        if (j < i) {
            int nb = buf ^ 1;
            const __half* kg = Kg + (size_t)(j + 1) * 128 * DA;
            const __half* vg = Vg + (size_t)(j + 1) * 128 * D;
            cpa16s(sb + AK_OFF + nb * 10240 + (qr * KSTR + qc) * 2,     kg + qr * DA + qc);
            cpa16s(sb + AK_OFF + nb * 10240 + (qr * KSTR + qc + 8) * 2, kg + qr * DA + qc + 8);
#pragma unroll
            for (int kk = 0; kk < 8; kk++)
                cpa16s(sb + AV_OFF + nb * 34816 + (vr * VSTR + vvc + kk * 8) * 2,
                       vg + (size_t)vr * D + vvc + kk * 8);
            CP_COMMIT();
            asm volatile("cp.async.wait_group 1;\n" ::: "memory");
        } else {
            asm volatile("cp.async.wait_group 0;\n" ::: "memory");
        }
        __syncthreads();

        float sc[4][4][4];
#pragma unroll
        for (int a = 0; a < 4; a++)
#pragma unroll
            for (int b = 0; b < 4; b++)
#pragma unroll
                for (int r = 0; r < 4; r++) sc[a][b][r] = 0.f;

        uint32_t kb0 = sb + AK_OFF + (uint32_t)(buf * 10240)
                     + (uint32_t)(ws_n * 32 * KSTR * 2) + laK;
#pragma unroll
        for (int kc = 0; kc < 2; kc++) {
            unsigned qa[4][4], kb[4][2];
#pragma unroll
            for (int mt = 0; mt < 4; mt++)
                ldsm4(qa[mt][0], qa[mt][1], qa[mt][2], qa[mt][3],
                      qfb + (unsigned)((mt * 16 * KSTR + kc * 16) * 2));
#pragma unroll
            for (int p = 0; p < 2; p++) {
                unsigned u0, u1, u2, u3;
                ldsm4(u0, u1, u2, u3, kb0 + (unsigned)((p * 16 * KSTR + kc * 16) * 2));
                kb[2 * p][0] = u0;     kb[2 * p][1] = u2;
                kb[2 * p + 1][0] = u1; kb[2 * p + 1][1] = u3;
            }
#pragma unroll
            for (int mt = 0; mt < 4; mt++)
#pragma unroll
                for (int nt = 0; nt < 4; nt++)
                    MMA_F16(sc[mt][nt][0], sc[mt][nt][1], sc[mt][nt][2], sc[mt][nt][3],
                            qa[mt][0], qa[mt][1], qa[mt][2], qa[mt][3],
                            kb[nt][0], kb[nt][1]);
        }

        bool diag = (j == i);
#pragma unroll
        for (int mt = 0; mt < 4; mt++) {
#pragma unroll
            for (int rp = 0; rp < 2; rp++) {
                int row = ws_m * 64 + mt * 16 + group + rp * 8;
#pragma unroll
                for (int nt = 0; nt < 4; nt++) {
                    int colb = ws_n * 32 + nt * 8 + tg * 2;
                    float v0 = sc[mt][nt][rp * 2], v1 = sc[mt][nt][rp * 2 + 1];
                    if (diag) {
                        if (colb > row) v0 = 0.f;
                        if (colb + 1 > row) v1 = 0.f;
                    }
                    __half2 hv = __floats2half2_rn(v0, v1);
                    float2 fb = __half22float2(hv);
                    dpart[mt * 2 + rp] += fb.x + fb.y;
                    *(__half2*)(smc + AS_OFF + ((size_t)row * SSTR + colb) * 2) = hv;
                }
            }
        }
        __syncthreads();

        uint32_t vb0 = sb + AV_OFF + (uint32_t)(buf * 34816)
                     + (uint32_t)(ws_n * 32 * 2) + laV;
#pragma unroll
        for (int kc = 0; kc < 8; kc++) {
            unsigned sa[4][4], vb[4][2];
#pragma unroll
            for (int mt = 0; mt < 4; mt++)
                ldsm4(sa[mt][0], sa[mt][1], sa[mt][2], sa[mt][3],
                      sfb + (unsigned)((mt * 16 * SSTR + kc * 16) * 2));
#pragma unroll
            for (int p = 0; p < 2; p++) {
                unsigned u0, u1, u2, u3;
                ldsm4t(u0, u1, u2, u3,
                       vb0 + (unsigned)((kc * 16 * VSTR + p * 16) * 2));
                vb[2 * p][0] = u0;     vb[2 * p][1] = u1;
                vb[2 * p + 1][0] = u2; vb[2 * p + 1][1] = u3;
            }
#pragma unroll
            for (int mt = 0; mt < 4; mt++)
#pragma unroll
                for (int nt = 0; nt < 4; nt++)
                    MMA_F16(oc[mt][nt][0], oc[mt][nt][1], oc[mt][nt][2], oc[mt][nt][3],
                            sa[mt][0], sa[mt][1], sa[mt][2], sa[mt][3],
                            vb[nt][0], vb[nt][1]);
        }
        __syncthreads();
    }

#pragma unroll
    for (int mt = 0; mt < 4; mt++)
#pragma unroll
        for (int rp = 0; rp < 2; rp++) {
            int m = i * 128 + ws_m * 64 + mt * 16 + group + rp * 8;
#pragma unroll
            for (int nt = 0; nt < 4; nt++) {
                int dd = d0 + ws_n * 32 + nt * 8 + tg * 2;
                *(float2*)&qkvh[((size_t)h * L + m) * D + dd] =
                    make_float2(oc[mt][nt][rp * 2], oc[mt][nt][rp * 2 + 1]);
            }
        }

#pragma unroll
    for (int q = 0; q < 8; q++) {
        float v = dpart[q];
        v += __shfl_xor_sync(0xffffffffu, v, 1, 4);
        v += __shfl_xor_sync(0xffffffffu, v, 2, 4);
        dpart[q] = v;
    }
    if (tg == 0) {
#pragma unroll
        for (int mt = 0; mt < 4; mt++)
#pragma unroll
            for (int rp = 0; rp < 2; rp++) {
                int row = ws_m * 64 + mt * 16 + group + rp * 8;
                dn[ws_n * 128 + row] = dpart[mt * 2 + rp];
            }
    }
    __syncthreads();
    if (blockIdx.x == 0 && tid < 128)
        den[h * L + i * 128 + tid] = dn[tid] + dn[128 + tid] + dn[256 + tid] + dn[384 + tid];
}

// -------- y = x + LN1(qkv/den), fp16 output --------
__global__ void y_kernel(const float* __restrict__ x, const float* __restrict__ qkvh,
                         const float* __restrict__ den, const float* __restrict__ w,
                         const float* __restrict__ b, __half* __restrict__ y)
{
    int l = blockIdx.x, tid = threadIdx.x;
    float t[8];
    float s = 0.f, s2 = 0.f;
#pragma unroll
    for (int r = 0; r < 8; r++) {
        int j = tid + r * 512;
        int h = j & 7, d = j >> 3;
        float v = qkvh[((size_t)(h * L + l)) * D + d] / den[h * L + l];
        t[r] = v; s += v; s2 += v * v;
    }
    float2 red = block_reduce2(s, s2);
    float mu = red.x * (1.0f / DH);
    float rs = rsqrtf(red.y * (1.0f / DH) - mu * mu + 1e-5f);
#pragma unroll
    for (int r = 0; r < 8; r++) {
        int j = tid + r * 512;
        y[(size_t)l * DH + j] =
            __float2half_rn(x[(size_t)l * D + (j >> 3)] + (t[r] - mu) * rs * w[j] + b[j]);
    }
}

__global__ void reduce_h1(const float* __restrict__ part, const float* __restrict__ b1,
                          __half* __restrict__ h1)
{
    int q = blockIdx.x * 256 + threadIdx.x;
    const float4* p = (const float4*)part;
    float4 v0 = p[q];
    float4 v1 = p[q + (L * FF / 4)];
    float4 bb = ((const float4*)b1)[q & (FF / 4 - 1)];
    __half2* H = (__half2*)h1;
    H[q * 2]     = __floats2half2_rn(fmaxf(v0.x + v1.x + bb.x, 0.f),
                                     fmaxf(v0.y + v1.y + bb.y, 0.f));
    H[q * 2 + 1] = __floats2half2_rn(fmaxf(v0.z + v1.z + bb.z, 0.f),
                                     fmaxf(v0.w + v1.w + bb.w, 0.f));
}

__global__ void reduce_out(const float* __restrict__ part, const float* __restrict__ b2,
                           const float* __restrict__ x, float* __restrict__ out)
{
    int q = blockIdx.x * 256 + threadIdx.x;
    const float4* p = (const float4*)part;
    float4 v0 = p[q];
    float4 v1 = p[q + 131072];
    float4 v2 = p[q + 262144];
    float4 v3 = p[q + 393216];
    float4 bb = ((const float4*)b2)[q & 127];
    float4 xx = ((const float4*)x)[q];
    float4 o;
    o.x = fmaxf(v0.x + v1.x + v2.x + v3.x + bb.x, 0.f) + xx.x;
    o.y = fmaxf(v0.y + v1.y + v2.y + v3.y + bb.y, 0.f) + xx.y;
    o.z = fmaxf(v0.z + v1.z + v2.z + v3.z + bb.z, 0.f) + xx.z;
    o.w = fmaxf(v0.w + v1.w + v2.w + v3.w + bb.w, 0.f) + xx.w;
    ((float4*)out)[q] = o;
}

extern "C" void kernel_launch(void* const* d_in, const int* in_sizes, int n_in,
                              void* d_out, int out_size)
{
    const float* x    = (const float*)d_in[0];
    const float* ln0w = (const float*)d_in[1];
    const float* ln0b = (const float*)d_in[2];
    const float* ln1w = (const float*)d_in[3];
    const float* ln1b = (const float*)d_in[4];
    const float* qw   = (const float*)d_in[5];
    const float* qb   = (const float*)d_in[6];
    const float* kw   = (const float*)d_in[7];
    const float* kb   = (const float*)d_in[8];
    const float* vw   = (const float*)d_in[9];
    const float* vb   = (const float*)d_in[10];
    const float* w1   = (const float*)d_in[11];
    const float* b1   = (const float*)d_in[12];
    const float* w2   = (const float*)d_in[13];
    const float* b2   = (const float*)d_in[14];
    float* out = (float*)d_out;

    __half *hx, *xnh, *hqw, *hkw, *hvw, *hw1, *hw2, *yh, *h1h, *qh, *kh, *vh;
    float *den, *qkvh, *part, *parth, *partq, *partk;
    cudaGetSymbolAddress((void**)&hx,    g_hx);
    cudaGetSymbolAddress((void**)&xnh,   g_xnh);
    cudaGetSymbolAddress((void**)&hqw,   g_hqw);
    cudaGetSymbolAddress((void**)&hkw,   g_hkw);
    cudaGetSymbolAddress((void**)&hvw,   g_hvw);
    cudaGetSymbolAddress((void**)&hw1,   g_hw1);
    cudaGetSymbolAddress((void**)&hw2,   g_hw2);
    cudaGetSymbolAddress((void**)&yh,    g_yh);
    cudaGetSymbolAddress((void**)&h1h,   g_h1h);
    cudaGetSymbolAddress((void**)&qh,    g_qh);
    cudaGetSymbolAddress((void**)&kh,    g_kh);
    cudaGetSymbolAddress((void**)&vh,    g_vh);
    cudaGetSymbolAddress((void**)&den,   g_den);
    cudaGetSymbolAddress((void**)&qkvh,  g_qkvh);
    cudaGetSymbolAddress((void**)&part,  g_part);
    cudaGetSymbolAddress((void**)&parth, g_parth);
    cudaGetSymbolAddress((void**)&partq, g_partq);
    cudaGetSymbolAddress((void**)&partk, g_partk);

    cudaFuncSetAttribute(fused_proj, cudaFuncAttributeMaxDynamicSharedMemorySize, HG_SMEM);
    cudaFuncSetAttribute(hgemm<2>, cudaFuncAttributeMaxDynamicSharedMemorySize, HG_SMEM);
    cudaFuncSetAttribute(attn_kernel, cudaFuncAttributeMaxDynamicSharedMemorySize, ATTN_SMEM);

    // 0+1) fused: fp16-convert weights+x, LN0 -> fp16
    conv_ln0<<<13056, 256>>>(qw, kw, vw, w1, w2, x, ln0w, ln0b,
                             hqw, hkw, hvw, hw1, hw2, hx, xnh);
    // 2+3) fused projections: z=1 v-proj (256 CTAs), z=0 q/k dual-splitK (16 CTAs)
    fused_proj<<<dim3(32, 8, 2), 128, HG_SMEM>>>(
        hx, hvw, vb, vh, xnh, hqw, hkw, partq, partk);
    // 2b) q,k = fp16(exp(clip(sum+bias) - 4)), head-major
    reduce_qk<<<dim3(1024, 2), 256>>>(partq, partk, qb, kb, qh, kh);
    // 4-6) fused attention (fp16, d-tile 128)
    attn_kernel<<<dim3(4, 8, NH), 256, ATTN_SMEM>>>(qh, kh, vh, qkvh, den);
    // 7) y = x + LN1(qkv/den) -> fp16
    y_kernel<<<L, 512>>>(x, qkvh, den, ln1w, ln1b, yh);
    // 8) h1 partials: splitK=2 of y@w1
    hgemm<2><<<dim3(FF/128, L/128, 2), 128, HG_SMEM>>>(
        yh, hw1, parth, L, FF, DH/2, DH, FF);
    // 8b) h1 = relu(sum + b1) -> fp16
    reduce_h1<<<2048, 256>>>(parth, b1, h1h);
    // 9) w2 partials: splitK=4
    hgemm<2><<<dim3(D/128, L/128, 4), 128, HG_SMEM>>>(
        h1h, hw2, part, L, D, FF/4, FF, D);
    // 10) out = relu(sum+b2)+x
    reduce_out<<<512, 256>>>(part, b2, x, out);
}

// round 14
// speedup vs baseline: 1.2515x; 1.0531x over previous
#include <cuda_runtime.h>
#include <cuda_fp16.h>
#include <math.h>
#include <stdint.h>

#define L  1024
#define D  512
#define NH 8
#define DA 32
#define AH 256
#define DH 4096
#define FF 2048

// -------- scratch --------
__device__ __half g_hx[L * D];
__device__ __half g_xnh[L * D];
__device__ __half g_hqw[D * AH];
__device__ __half g_hkw[D * AH];
__device__ __half g_hvw[D * DH];
__device__ __half g_hw1[DH * FF];
__device__ __half g_hw2[FF * D];
__device__ __half g_yh[(size_t)L * DH];
__device__ __half g_h1h[L * FF];
__device__ __half g_qh[NH * L * DA];
__device__ __half g_kh[NH * L * DA];
__device__ __half g_vh[NH * L * D];
__device__ float g_den[NH * L];
__device__ float g_qkvh[NH * L * D];
__device__ float g_part[4 * L * D];
__device__ float g_parth[2 * L * FF];
__device__ float g_partq[4 * L * AH];
__device__ float g_partk[4 * L * AH];

__device__ __forceinline__ void cpa16s(unsigned sa, const void* g) {
    asm volatile("cp.async.cg.shared.global [%0], [%1], 16;\n" :: "r"(sa), "l"(g));
}
#define CP_COMMIT() asm volatile("cp.async.commit_group;\n" ::: "memory")
#define CP_WAIT2()  asm volatile("cp.async.wait_group 2;\n" ::: "memory")

__device__ __forceinline__ void ldsm4(unsigned& r0, unsigned& r1, unsigned& r2, unsigned& r3,
                                      unsigned addr) {
    asm volatile("ldmatrix.sync.aligned.m8n8.x4.shared.b16 {%0,%1,%2,%3}, [%4];"
                 : "=r"(r0), "=r"(r1), "=r"(r2), "=r"(r3) : "r"(addr));
}
__device__ __forceinline__ void ldsm4t(unsigned& r0, unsigned& r1, unsigned& r2, unsigned& r3,
                                       unsigned addr) {
    asm volatile("ldmatrix.sync.aligned.m8n8.x4.trans.shared.b16 {%0,%1,%2,%3}, [%4];"
                 : "=r"(r0), "=r"(r1), "=r"(r2), "=r"(r3) : "r"(addr));
}

#define MMA_F16(c0,c1,c2,c3,a0,a1,a2,a3,b0,b1) \
    asm volatile("mma.sync.aligned.m16n8k16.row.col.f32.f16.f16.f32 " \
        "{%0,%1,%2,%3}, {%4,%5,%6,%7}, {%8,%9}, {%0,%1,%2,%3};" \
        : "+f"(c0), "+f"(c1), "+f"(c2), "+f"(c3) \
        : "r"(a0), "r"(a1), "r"(a2), "r"(a3), "r"(b0), "r"(b1))

__device__ __forceinline__ float2 block_reduce2(float a, float b) {
    __shared__ float2 sh[16];
    int tid = threadIdx.x;
#pragma unroll
    for (int o = 16; o > 0; o >>= 1) {
        a += __shfl_down_sync(0xffffffffu, a, o);
        b += __shfl_down_sync(0xffffffffu, b, o);
    }
    int wid = tid >> 5, lane = tid & 31;
    int nw = blockDim.x >> 5;
    if (lane == 0) sh[wid] = make_float2(a, b);
    __syncthreads();
    if (wid == 0) {
        float2 v = (lane < nw) ? sh[lane] : make_float2(0.f, 0.f);
        a = v.x; b = v.y;
#pragma unroll
        for (int o = 8; o > 0; o >>= 1) {
            a += __shfl_down_sync(0xffffffffu, a, o);
            b += __shfl_down_sync(0xffffffffu, b, o);
        }
        if (lane == 0) sh[0] = make_float2(a, b);
    }
    __syncthreads();
    return sh[0];
}

// -------- fused: fp16 conversion of weights+x AND LN0(x)->fp16 --------
__global__ void conv_ln0(const float* __restrict__ qw, const float* __restrict__ kw,
                         const float* __restrict__ vw, const float* __restrict__ w1,
                         const float* __restrict__ w2, const float* __restrict__ x,
                         const float* __restrict__ ln0w, const float* __restrict__ ln0b,
                         __half* hqw, __half* hkw, __half* hvw, __half* hw1, __half* hw2,
                         __half* hx, __half* xnh)
{
    int t = blockIdx.x;
    int tid = threadIdx.x;
    if (t < 12032) {
        int q = t * 256 + tid;
        const float4* s; __half* d; int off;
        if (q < 32768)        { s = (const float4*)qw; d = hqw; off = q; }
        else if (q < 65536)   { s = (const float4*)kw; d = hkw; off = q - 32768; }
        else if (q < 589824)  { s = (const float4*)vw; d = hvw; off = q - 65536; }
        else if (q < 2686976) { s = (const float4*)w1; d = hw1; off = q - 589824; }
        else if (q < 2949120) { s = (const float4*)w2; d = hw2; off = q - 2686976; }
        else                  { s = (const float4*)x;  d = hx;  off = q - 2949120; }
        float4 v = s[off];
        __half2* d2 = (__half2*)d;
        d2[off * 2]     = __floats2half2_rn(v.x, v.y);
        d2[off * 2 + 1] = __floats2half2_rn(v.z, v.w);
        return;
    }
    int l = t - 12032;
    const float* row = x + (size_t)l * D;
    float v0 = row[tid], v1 = row[tid + 256];
    float2 r = block_reduce2(v0 + v1, v0 * v0 + v1 * v1);
    float mu = r.x * (1.0f / D);
    float var = r.y * (1.0f / D) - mu * mu;
    float rs = rsqrtf(var + 1e-5f);
    xnh[(size_t)l * D + tid]       = __float2half_rn((v0 - mu) * rs * ln0w[tid] + ln0b[tid]);
    xnh[(size_t)l * D + tid + 256] = __float2half_rn((v1 - mu) * rs * ln0w[tid + 256] + ln0b[tid + 256]);
}

// ========== fp16 tensor GEMM mainloop (device fn): 128x128x32 tiles, 4 warps ==========
#define HG_ASTR 40
#define HG_BSTR 136
#define HG_ABYT (128 * HG_ASTR * 2)
#define HG_STG  (HG_ABYT + 32 * HG_BSTR * 2)
#define HG_SMEM (4 * HG_STG)
#define PH_STRIDE (128 * 16 + 8)

__device__ __forceinline__ void hg_main(
    uint32_t sbase, const __half* __restrict__ A, const __half* __restrict__ B,
    int N, int K, int lda, int ldb, int m0, int n0, float (&c)[4][8][4])
{
    int tid = threadIdx.x;
    int wid = tid >> 5, lane = tid & 31;
    int warp_m = wid >> 1, warp_n = wid & 1;
    int kTiles = K / 32;

    const __half* Ab = A + (size_t)(m0 + tid) * lda;
    int br = tid >> 2, bc = (tid & 3) * 32;
    const __half* Bb = B + n0 + bc;

    uint32_t laA = ((lane & 15) * HG_ASTR + ((lane >> 4) << 3)) * 2;
    uint32_t laB = ((lane & 15) * HG_BSTR + ((lane >> 4) << 3)) * 2;
    uint32_t afw = (uint32_t)(warp_m * 64 * HG_ASTR * 2) + laA;
    uint32_t bfw = (uint32_t)(warp_n * 64 * 2) + laB;

#pragma unroll
    for (int i = 0; i < 4; i++)
#pragma unroll
        for (int j = 0; j < 8; j++)
#pragma unroll
            for (int r = 0; r < 4; r++) c[i][j][r] = 0.f;

#pragma unroll
    for (int s = 0; s < 3; s++) {
        if (s < kTiles) {
            uint32_t sA = sbase + s * HG_STG;
            uint32_t sB = sA + HG_ABYT;
#pragma unroll
            for (int cc = 0; cc < 4; cc++)
                cpa16s(sA + (tid * HG_ASTR + cc * 8) * 2, Ab + s * 32 + cc * 8);
#pragma unroll
            for (int cc = 0; cc < 4; cc++)
                cpa16s(sB + (br * HG_BSTR + bc + cc * 8) * 2,
                       Bb + (size_t)(s * 32 + br) * ldb + cc * 8);
        }
        CP_COMMIT();
    }
    CP_WAIT2();
    __syncthreads();

    for (int t = 0; t < kTiles; t++) {
        int tp = t + 3;
        if (tp < kTiles) {
            int ps = tp & 3;
            uint32_t sA = sbase + ps * HG_STG;
            uint32_t sB = sA + HG_ABYT;
#pragma unroll
            for (int cc = 0; cc < 4; cc++)
                cpa16s(sA + (tid * HG_ASTR + cc * 8) * 2, Ab + tp * 32 + cc * 8);
#pragma unroll
            for (int cc = 0; cc < 4; cc++)
                cpa16s(sB + (br * HG_BSTR + bc + cc * 8) * 2,
                       Bb + (size_t)(tp * 32 + br) * ldb + cc * 8);
        }
        CP_COMMIT();

        uint32_t aSt = sbase + (t & 3) * HG_STG + afw;
        uint32_t bSt = sbase + (t & 3) * HG_STG + HG_ABYT + bfw;

        unsigned a[2][4][4], b[2][8][2];
#pragma unroll
        for (int kk = 0; kk < 2; kk++) {
#pragma unroll
            for (int mt = 0; mt < 4; mt++)
                ldsm4(a[kk][mt][0], a[kk][mt][1], a[kk][mt][2], a[kk][mt][3],
                      aSt + (unsigned)((mt * 16 * HG_ASTR + kk * 16) * 2));
#pragma unroll
            for (int p = 0; p < 4; p++) {
                unsigned u0, u1, u2, u3;
                ldsm4t(u0, u1, u2, u3,
                       bSt + (unsigned)((p * 16) * 2 + (kk * 16 * HG_BSTR) * 2));
                b[kk][2 * p][0] = u0;     b[kk][2 * p][1] = u1;
                b[kk][2 * p + 1][0] = u2; b[kk][2 * p + 1][1] = u3;
            }
        }
#pragma unroll
        for (int kk = 0; kk < 2; kk++)
#pragma unroll
            for (int mt = 0; mt < 4; mt++)
#pragma unroll
                for (int nt = 0; nt < 8; nt++)
                    MMA_F16(c[mt][nt][0], c[mt][nt][1], c[mt][nt][2], c[mt][nt][3],
                            a[kk][mt][0], a[kk][mt][1], a[kk][mt][2], a[kk][mt][3],
                            b[kk][nt][0], b[kk][nt][1]);

        CP_WAIT2();
        __syncthreads();
    }
}

template<int EPI>
__device__ __forceinline__ void epi_plain(
    float (&c)[4][8][4], const float* __restrict__ bias,
    float* __restrict__ C, int N, int m0, int n0)
{
    int tid = threadIdx.x;
    int wid = tid >> 5, lane = tid & 31;
    int group = lane >> 2, tg = lane & 3;
    int warp_m = wid >> 1, warp_n = wid & 1;
#pragma unroll
    for (int mt = 0; mt < 4; mt++)
#pragma unroll
        for (int nt = 0; nt < 8; nt++)
#pragma unroll
            for (int r = 0; r < 4; r++) {
                int m = m0 + warp_m * 64 + mt * 16 + group + (r >> 1) * 8;
                int n = n0 + warp_n * 64 + nt * 8 + tg * 2 + (r & 1);
                float v = c[mt][nt][r];
                if (EPI == 2) v = v + bias[n];
                else if (EPI == 3) v = fmaxf(v + bias[n], 0.f);
                C[(size_t)m * N + n] = v;
            }
}

__device__ __forceinline__ void epi_perm_half(
    float (&c)[4][8][4], char* smemc, const float* __restrict__ bias,
    __half* __restrict__ Ch, int M, int N, int m0, int n0)
{
    int tid = threadIdx.x;
    int wid = tid >> 5, lane = tid & 31;
    int group = lane >> 2, tg = lane & 3;
    int warp_m = wid >> 1, warp_n = wid & 1;
    __syncthreads();
    __half* st = (__half*)smemc;
#pragma unroll
    for (int mt = 0; mt < 4; mt++)
#pragma unroll
        for (int nt = 0; nt < 8; nt++)
#pragma unroll
            for (int r = 0; r < 4; r++) {
                int row = warp_m * 64 + mt * 16 + group + (r >> 1) * 8;
                int n = warp_n * 64 + nt * 8 + tg * 2 + (r & 1);
                float v = c[mt][nt][r] + bias[n0 + n];
                st[(n & 7) * PH_STRIDE + row * 16 + (n >> 3)] = __float2half_rn(v);
            }
    __syncthreads();
    int NI = N >> 3;
#pragma unroll
    for (int it = 0; it < 16; it++) {
        int cidx = it * 128 + tid;
        int h = cidx >> 8;
        int m = (cidx >> 1) & 127;
        int ck = cidx & 1;
        uint4 v = *(uint4*)&st[h * PH_STRIDE + m * 16 + ck * 8];
        *(uint4*)&Ch[((size_t)(h * M + m0 + m)) * NI + (n0 >> 3) + ck * 8] = v;
    }
}

// ========== fused projection launch ==========
__global__ void __launch_bounds__(128, 2) fused_proj(
    const __half* __restrict__ hx, const __half* __restrict__ hvw,
    const float* __restrict__ vb, __half* __restrict__ vh,
    const __half* __restrict__ xnh, const __half* __restrict__ hqw,
    const __half* __restrict__ hkw, float* __restrict__ partq,
    float* __restrict__ partk)
{
    extern __shared__ char smemc[];
    uint32_t sbase = (uint32_t)__cvta_generic_to_shared(smemc);
    float c[4][8][4];
    int m0 = blockIdx.y * 128;

    if (blockIdx.z == 1) {
        int n0 = blockIdx.x * 128;
        hg_main(sbase, hx, hvw, DH, D, D, DH, m0, n0, c);
        epi_perm_half(c, smemc, vb, vh, L, DH, m0, n0);
    } else {
        int bx = blockIdx.x;
        if (bx >= 16) return;
        int xt = bx & 1, ks = (bx >> 1) & 3, set = bx >> 3;
        const __half* A = xnh + ks * 128;
        const __half* B = (set ? hkw : hqw) + (size_t)ks * 128 * AH;
        float* C = (set ? partk : partq) + (size_t)ks * L * AH;
        int n0 = xt * 128;
        hg_main(sbase, A, B, AH, 128, D, AH, m0, n0, c);
        epi_plain<0>(c, nullptr, C, AH, m0, n0);
    }
}

// ========== standalone hgemm for FFN (splitK fp32-out) ==========
template<int MODE>
__global__ void __launch_bounds__(128, 2) hgemm(
    const __half* __restrict__ A, const __half* __restrict__ B,
    float* __restrict__ C, int M, int N, int K, int lda, int ldb)
{
    extern __shared__ char smemc[];
    uint32_t sbase = (uint32_t)__cvta_generic_to_shared(smemc);
    int z = blockIdx.z;
    if (MODE == 2) {
        A += (size_t)z * K;
        B += (size_t)z * K * ldb;
        C += (size_t)z * M * N;
    }
    float c[4][8][4];
    int m0 = blockIdx.y * 128, n0 = blockIdx.x * 128;
    hg_main(sbase, A, B, N, K, lda, ldb, m0, n0, c);
    epi_plain<0>(c, nullptr, C, N, m0, n0);
}

// -------- split-K reduce for q/k: fp16(exp(clip(sum+bias) - 4)), head-major --------
__global__ void reduce_qk(const float* __restrict__ pq, const float* __restrict__ pk,
                          const float* __restrict__ qb, const float* __restrict__ kb,
                          __half* __restrict__ qh, __half* __restrict__ kh)
{
    int set = blockIdx.y;
    const float* p   = set ? pk : pq;
    const float* bia = set ? kb : qb;
    __half* o = set ? kh : qh;
    int i = blockIdx.x * 256 + threadIdx.x;
    int m = i >> 8, n = i & 255;
    float s = p[i] + p[i + 262144] + p[i + 524288] + p[i + 786432] + bia[n];
    s = expf(fminf(fmaxf(s, -10.f), 10.f) - 4.0f);
    int h = n & 7, inner = n >> 3;
    o[((size_t)(h * L + m)) * DA + inner] = __float2half_rn(s);
}

// ================= persistent snake-balanced fused flash attention =================
// 128 CTAs; CTA c runs tasks {c, 255-c}; task t: i = 7-(t>>5), h = (t&31)>>2, dtile = t&3.
#define AQ_OFF 0
#define AK_OFF 10240
#define AV_OFF 30720
#define AS_OFF 100352
#define ADN_OFF 135168
#define ATTN_SMEM 137216
#define KSTR 40
#define VSTR 136
#define SSTR 136

__global__ void __launch_bounds__(256, 1) attn_kernel(
    const __half* __restrict__ qhp, const __half* __restrict__ khp,
    const __half* __restrict__ vhp, float* __restrict__ qkvh,
    float* __restrict__ den)
{
    extern __shared__ char smc[];
    uint32_t sb = (uint32_t)__cvta_generic_to_shared(smc);
    float* dn = (float*)(smc + ADN_OFF);

    int tid = threadIdx.x, lane = tid & 31, wid = tid >> 5;
    int group = lane >> 2, tg = lane & 3;
    int ws_m = wid >> 2, ws_n = wid & 3;

    uint32_t laK = ((lane & 15) * KSTR + ((lane >> 4) << 3)) * 2;
    uint32_t laV = ((lane & 15) * VSTR + ((lane >> 4) << 3)) * 2;
    uint32_t qfb = sb + AQ_OFF + (uint32_t)(ws_m * 64 * KSTR * 2) + laK;
    uint32_t sfb = sb + AS_OFF + (uint32_t)(ws_m * 64 * SSTR * 2)
                 + ((lane & 15) * SSTR + ((lane >> 4) << 3)) * 2;
    int qr = tid >> 1, qc = (tid & 1) * 16;
    int vr = tid >> 1, vvc = (tid & 1) * 64;

#pragma unroll 1
    for (int slot = 0; slot < 2; slot++) {
        int t = (slot == 0) ? (int)blockIdx.x : 255 - (int)blockIdx.x;
        int i = 7 - (t >> 5);
        int sub = t & 31;
        int h = sub >> 2;
        int d0 = (sub & 3) * 128;

        __syncthreads();   // protect dn/smem from previous task

        const __half* Qg = qhp + ((size_t)h * L + i * 128) * DA;
        const __half* Kg = khp + (size_t)h * L * DA;
        const __half* Vg = vhp + (size_t)h * L * D + d0;

        if (tid < 128) { dn[tid] = 0.f; dn[128 + tid] = 0.f; dn[256 + tid] = 0.f; dn[384 + tid] = 0.f; }

        cpa16s(sb + AQ_OFF + (qr * KSTR + qc) * 2,     Qg + qr * DA + qc);
        cpa16s(sb + AQ_OFF + (qr * KSTR + qc + 8) * 2, Qg + qr * DA + qc + 8);
        CP_COMMIT();
        cpa16s(sb + AK_OFF + (qr * KSTR + qc) * 2,     Kg + qr * DA + qc);
        cpa16s(sb + AK_OFF + (qr * KSTR + qc + 8) * 2, Kg + qr * DA + qc + 8);
#pragma unroll
        for (int kk = 0; kk < 8; kk++)
            cpa16s(sb + AV_OFF + (vr * VSTR + vvc + kk * 8) * 2,
                   Vg + (size_t)vr * D + vvc + kk * 8);
        CP_COMMIT();

        float oc[4][4][4];
#pragma unroll
        for (int a = 0; a < 4; a++)
#pragma unroll
            for (int b = 0; b < 4; b++)
#pragma unroll
                for (int r = 0; r < 4; r++) oc[a][b][r] = 0.f;
        float dpart[8];
#pragma unroll
        for (int a = 0; a < 8; a++) dpart[a] = 0.f;

        for (int j = 0; j <= i; j++) {
            int buf = j & 1;
            if (j < i) {
                int nb = buf ^ 1;
                const __half* kg = Kg + (size_t)(j + 1) * 128 * DA;
                const __half* vg = Vg + (size_t)(j + 1) * 128 * D;
                cpa16s(sb + AK_OFF + nb * 10240 + (qr * KSTR + qc) * 2,     kg + qr * DA + qc);
                cpa16s(sb + AK_OFF + nb * 10240 + (qr * KSTR + qc + 8) * 2, kg + qr * DA + qc + 8);
#pragma unroll
                for (int kk = 0; kk < 8; kk++)
                    cpa16s(sb + AV_OFF + nb * 34816 + (vr * VSTR + vvc + kk * 8) * 2,
                           vg + (size_t)vr * D + vvc + kk * 8);
                CP_COMMIT();
                asm volatile("cp.async.wait_group 1;\n" ::: "memory");
            } else {
                asm volatile("cp.async.wait_group 0;\n" ::: "memory");
            }
            __syncthreads();

            float sc[4][4][4];
#pragma unroll
            for (int a = 0; a < 4; a++)
#pragma unroll
                for (int b = 0; b < 4; b++)
#pragma unroll
                    for (int r = 0; r < 4; r++) sc[a][b][r] = 0.f;

            uint32_t kb0 = sb + AK_OFF + (uint32_t)(buf * 10240)
                         + (uint32_t)(ws_n * 32 * KSTR * 2) + laK;
#pragma unroll
            for (int kc = 0; kc < 2; kc++) {
                unsigned qa[4][4], kb[4][2];
#pragma unroll
                for (int mt = 0; mt < 4; mt++)
                    ldsm4(qa[mt][0], qa[mt][1], qa[mt][2], qa[mt][3],
                          qfb + (unsigned)((mt * 16 * KSTR + kc * 16) * 2));
#pragma unroll
                for (int p = 0; p < 2; p++) {
                    unsigned u0, u1, u2, u3;
                    ldsm4(u0, u1, u2, u3, kb0 + (unsigned)((p * 16 * KSTR + kc * 16) * 2));
                    kb[2 * p][0] = u0;     kb[2 * p][1] = u2;
                    kb[2 * p + 1][0] = u1; kb[2 * p + 1][1] = u3;
                }
#pragma unroll
                for (int mt = 0; mt < 4; mt++)
#pragma unroll
                    for (int nt = 0; nt < 4; nt++)
                        MMA_F16(sc[mt][nt][0], sc[mt][nt][1], sc[mt][nt][2], sc[mt][nt][3],
                                qa[mt][0], qa[mt][1], qa[mt][2], qa[mt][3],
                                kb[nt][0], kb[nt][1]);
            }

            bool diag = (j == i);
#pragma unroll
            for (int mt = 0; mt < 4; mt++) {
#pragma unroll
                for (int rp = 0; rp < 2; rp++) {
                    int row = ws_m * 64 + mt * 16 + group + rp * 8;
#pragma unroll
                    for (int nt = 0; nt < 4; nt++) {
                        int colb = ws_n * 32 + nt * 8 + tg * 2;
                        float v0 = sc[mt][nt][rp * 2], v1 = sc[mt][nt][rp * 2 + 1];
                        if (diag) {
                            if (colb > row) v0 = 0.f;
                            if (colb + 1 > row) v1 = 0.f;
                        }
                        __half2 hv = __floats2half2_rn(v0, v1);
                        float2 fb = __half22float2(hv);
                        dpart[mt * 2 + rp] += fb.x + fb.y;
                        *(__half2*)(smc + AS_OFF + ((size_t)row * SSTR + colb) * 2) = hv;
                    }
                }
            }
            __syncthreads();

            uint32_t vb0 = sb + AV_OFF + (uint32_t)(buf * 34816)
                         + (uint32_t)(ws_n * 32 * 2) + laV;
#pragma unroll
            for (int kc = 0; kc < 8; kc++) {
                unsigned sa[4][4], vb[4][2];
#pragma unroll
                for (int mt = 0; mt < 4; mt++)
                    ldsm4(sa[mt][0], sa[mt][1], sa[mt][2], sa[mt][3],
                          sfb + (unsigned)((mt * 16 * SSTR + kc * 16) * 2));
#pragma unroll
                for (int p = 0; p < 2; p++) {
                    unsigned u0, u1, u2, u3;
                    ldsm4t(u0, u1, u2, u3,
                           vb0 + (unsigned)((kc * 16 * VSTR + p * 16) * 2));
                    vb[2 * p][0] = u0;     vb[2 * p][1] = u1;
                    vb[2 * p + 1][0] = u2; vb[2 * p + 1][1] = u3;
                }
#pragma unroll
                for (int mt = 0; mt < 4; mt++)
#pragma unroll
                    for (int nt = 0; nt < 4; nt++)
                        MMA_F16(oc[mt][nt][0], oc[mt][nt][1], oc[mt][nt][2], oc[mt][nt][3],
                                sa[mt][0], sa[mt][1], sa[mt][2], sa[mt][3],
                                vb[nt][0], vb[nt][1]);
            }
            __syncthreads();
        }

#pragma unroll
        for (int mt = 0; mt < 4; mt++)
#pragma unroll
            for (int rp = 0; rp < 2; rp++) {
                int m = i * 128 + ws_m * 64 + mt * 16 + group + rp * 8;
#pragma unroll
                for (int nt = 0; nt < 4; nt++) {
                    int dd = d0 + ws_n * 32 + nt * 8 + tg * 2;
                    *(float2*)&qkvh[((size_t)h * L + m) * D + dd] =
                        make_float2(oc[mt][nt][rp * 2], oc[mt][nt][rp * 2 + 1]);
                }
            }

#pragma unroll
        for (int q = 0; q < 8; q++) {
            float v = dpart[q];
            v += __shfl_xor_sync(0xffffffffu, v, 1, 4);
            v += __shfl_xor_sync(0xffffffffu, v, 2, 4);
            dpart[q] = v;
        }
        if (tg == 0) {
#pragma unroll
            for (int mt = 0; mt < 4; mt++)
#pragma unroll
                for (int rp = 0; rp < 2; rp++) {
                    int row = ws_m * 64 + mt * 16 + group + rp * 8;
                    dn[ws_n * 128 + row] = dpart[mt * 2 + rp];
                }
        }
        __syncthreads();
        if ((sub & 3) == 0 && tid < 128)
            den[h * L + i * 128 + tid] = dn[tid] + dn[128 + tid] + dn[256 + tid] + dn[384 + tid];
    }
}

// -------- y = x + LN1(qkv/den), fp16 output --------
__global__ void y_kernel(const float* __restrict__ x, const float* __restrict__ qkvh,
                         const float* __restrict__ den, const float* __restrict__ w,
                         const float* __restrict__ b, __half* __restrict__ y)
{
    int l = blockIdx.x, tid = threadIdx.x;
    float t[8];
    float s = 0.f, s2 = 0.f;
#pragma unroll
    for (int r = 0; r < 8; r++) {
        int j = tid + r * 512;
        int h = j & 7, d = j >> 3;
        float v = qkvh[((size_t)(h * L + l)) * D + d] / den[h * L + l];
        t[r] = v; s += v; s2 += v * v;
    }
    float2 red = block_reduce2(s, s2);
    float mu = red.x * (1.0f / DH);
    float rs = rsqrtf(red.y * (1.0f / DH) - mu * mu + 1e-5f);
#pragma unroll
    for (int r = 0; r < 8; r++) {
        int j = tid + r * 512;
        y[(size_t)l * DH + j] =
            __float2half_rn(x[(size_t)l * D + (j >> 3)] + (t[r] - mu) * rs * w[j] + b[j]);
    }
}

__global__ void reduce_h1(const float* __restrict__ part, const float* __restrict__ b1,
                          __half* __restrict__ h1)
{
    int q = blockIdx.x * 256 + threadIdx.x;
    const float4* p = (const float4*)part;
    float4 v0 = p[q];
    float4 v1 = p[q + (L * FF / 4)];
    float4 bb = ((const float4*)b1)[q & (FF / 4 - 1)];
    __half2* H = (__half2*)h1;
    H[q * 2]     = __floats2half2_rn(fmaxf(v0.x + v1.x + bb.x, 0.f),
                                     fmaxf(v0.y + v1.y + bb.y, 0.f));
    H[q * 2 + 1] = __floats2half2_rn(fmaxf(v0.z + v1.z + bb.z, 0.f),
                                     fmaxf(v0.w + v1.w + bb.w, 0.f));
}

__global__ void reduce_out(const float* __restrict__ part, const float* __restrict__ b2,
                           const float* __restrict__ x, float* __restrict__ out)
{
    int q = blockIdx.x * 256 + threadIdx.x;
    const float4* p = (const float4*)part;
    float4 v0 = p[q];
    float4 v1 = p[q + 131072];
    float4 v2 = p[q + 262144];
    float4 v3 = p[q + 393216];
    float4 bb = ((const float4*)b2)[q & 127];
    float4 xx = ((const float4*)x)[q];
    float4 o;
    o.x = fmaxf(v0.x + v1.x + v2.x + v3.x + bb.x, 0.f) + xx.x;
    o.y = fmaxf(v0.y + v1.y + v2.y + v3.y + bb.y, 0.f) + xx.y;
    o.z = fmaxf(v0.z + v1.z + v2.z + v3.z + bb.z, 0.f) + xx.z;
    o.w = fmaxf(v0.w + v1.w + v2.w + v3.w + bb.w, 0.f) + xx.w;
    ((float4*)out)[q] = o;
}

extern "C" void kernel_launch(void* const* d_in, const int* in_sizes, int n_in,
                              void* d_out, int out_size)
{
    const float* x    = (const float*)d_in[0];
    const float* ln0w = (const float*)d_in[1];
    const float* ln0b = (const float*)d_in[2];
    const float* ln1w = (const float*)d_in[3];
    const float* ln1b = (const float*)d_in[4];
    const float* qw   = (const float*)d_in[5];
    const float* qb   = (const float*)d_in[6];
    const float* kw   = (const float*)d_in[7];
    const float* kb   = (const float*)d_in[8];
    const float* vw   = (const float*)d_in[9];
    const float* vb   = (const float*)d_in[10];
    const float* w1   = (const float*)d_in[11];
    const float* b1   = (const float*)d_in[12];
    const float* w2   = (const float*)d_in[13];
    const float* b2   = (const float*)d_in[14];
    float* out = (float*)d_out;

    __half *hx, *xnh, *hqw, *hkw, *hvw, *hw1, *hw2, *yh, *h1h, *qh, *kh, *vh;
    float *den, *qkvh, *part, *parth, *partq, *partk;
    cudaGetSymbolAddress((void**)&hx,    g_hx);
    cudaGetSymbolAddress((void**)&xnh,   g_xnh);
    cudaGetSymbolAddress((void**)&hqw,   g_hqw);
    cudaGetSymbolAddress((void**)&hkw,   g_hkw);
    cudaGetSymbolAddress((void**)&hvw,   g_hvw);
    cudaGetSymbolAddress((void**)&hw1,   g_hw1);
    cudaGetSymbolAddress((void**)&hw2,   g_hw2);
    cudaGetSymbolAddress((void**)&yh,    g_yh);
    cudaGetSymbolAddress((void**)&h1h,   g_h1h);
    cudaGetSymbolAddress((void**)&qh,    g_qh);
    cudaGetSymbolAddress((void**)&kh,    g_kh);
    cudaGetSymbolAddress((void**)&vh,    g_vh);
    cudaGetSymbolAddress((void**)&den,   g_den);
    cudaGetSymbolAddress((void**)&qkvh,  g_qkvh);
    cudaGetSymbolAddress((void**)&part,  g_part);
    cudaGetSymbolAddress((void**)&parth, g_parth);
    cudaGetSymbolAddress((void**)&partq, g_partq);
    cudaGetSymbolAddress((void**)&partk, g_partk);

    cudaFuncSetAttribute(fused_proj, cudaFuncAttributeMaxDynamicSharedMemorySize, HG_SMEM);
    cudaFuncSetAttribute(hgemm<2>, cudaFuncAttributeMaxDynamicSharedMemorySize, HG_SMEM);
    cudaFuncSetAttribute(attn_kernel, cudaFuncAttributeMaxDynamicSharedMemorySize, ATTN_SMEM);

    // 0+1) fused: fp16-convert weights+x, LN0 -> fp16
    conv_ln0<<<13056, 256>>>(qw, kw, vw, w1, w2, x, ln0w, ln0b,
                             hqw, hkw, hvw, hw1, hw2, hx, xnh);
    // 2+3) fused projections
    fused_proj<<<dim3(32, 8, 2), 128, HG_SMEM>>>(
        hx, hvw, vb, vh, xnh, hqw, hkw, partq, partk);
    // 2b) q,k = fp16(exp(clip(sum+bias) - 4)), head-major
    reduce_qk<<<dim3(1024, 2), 256>>>(partq, partk, qb, kb, qh, kh);
    // 4-6) persistent snake-balanced attention (128 CTAs, 1 wave, 9 units each)
    attn_kernel<<<128, 256, ATTN_SMEM>>>(qh, kh, vh, qkvh, den);
    // 7) y = x + LN1(qkv/den) -> fp16
    y_kernel<<<L, 512>>>(x, qkvh, den, ln1w, ln1b, yh);
    // 8) h1 partials: splitK=2 of y@w1
    hgemm<2><<<dim3(FF/128, L/128, 2), 128, HG_SMEM>>>(
        yh, hw1, parth, L, FF, DH/2, DH, FF);
    // 8b) h1 = relu(sum + b1) -> fp16
    reduce_h1<<<2048, 256>>>(parth, b1, h1h);
    // 9) w2 partials: splitK=4
    hgemm<2><<<dim3(D/128, L/128, 4), 128, HG_SMEM>>>(
        h1h, hw2, part, L, D, FF/4, FF, D);
    // 10) out = relu(sum+b2)+x
    reduce_out<<<512, 256>>>(part, b2, x, out);
}

// round 15
// speedup vs baseline: 1.3005x; 1.0392x over previous
#include <cuda_runtime.h>
#include <cuda_fp16.h>
#include <math.h>
#include <stdint.h>

#define L  1024
#define D  512
#define NH 8
#define DA 32
#define AH 256
#define DH 4096
#define FF 2048

// -------- scratch --------
__device__ __half g_hx[L * D];
__device__ __half g_xnh[L * D];
__device__ __half g_hqw[D * AH];
__device__ __half g_hkw[D * AH];
__device__ __half g_hvw[D * DH];
__device__ __half g_hw1[DH * FF];
__device__ __half g_hw2[FF * D];
__device__ __half g_yh[(size_t)L * DH];
__device__ __half g_h1h[L * FF];
__device__ __half g_qh[NH * L * DA];
__device__ __half g_kh[NH * L * DA];
__device__ __half g_vh[NH * L * D];
__device__ float g_den[NH * L];
__device__ float g_qkvh[NH * L * D];
__device__ float g_part[4 * L * D];
__device__ float g_parth[2 * L * FF];

__device__ __forceinline__ void cpa16s(unsigned sa, const void* g) {
    asm volatile("cp.async.cg.shared.global [%0], [%1], 16;\n" :: "r"(sa), "l"(g));
}
#define CP_COMMIT() asm volatile("cp.async.commit_group;\n" ::: "memory")
#define CP_WAIT2()  asm volatile("cp.async.wait_group 2;\n" ::: "memory")

__device__ __forceinline__ void ldsm4(unsigned& r0, unsigned& r1, unsigned& r2, unsigned& r3,
                                      unsigned addr) {
    asm volatile("ldmatrix.sync.aligned.m8n8.x4.shared.b16 {%0,%1,%2,%3}, [%4];"
                 : "=r"(r0), "=r"(r1), "=r"(r2), "=r"(r3) : "r"(addr));
}
__device__ __forceinline__ void ldsm4t(unsigned& r0, unsigned& r1, unsigned& r2, unsigned& r3,
                                       unsigned addr) {
    asm volatile("ldmatrix.sync.aligned.m8n8.x4.trans.shared.b16 {%0,%1,%2,%3}, [%4];"
                 : "=r"(r0), "=r"(r1), "=r"(r2), "=r"(r3) : "r"(addr));
}

#define MMA_F16(c0,c1,c2,c3,a0,a1,a2,a3,b0,b1) \
    asm volatile("mma.sync.aligned.m16n8k16.row.col.f32.f16.f16.f32 " \
        "{%0,%1,%2,%3}, {%4,%5,%6,%7}, {%8,%9}, {%0,%1,%2,%3};" \
        : "+f"(c0), "+f"(c1), "+f"(c2), "+f"(c3) \
        : "r"(a0), "r"(a1), "r"(a2), "r"(a3), "r"(b0), "r"(b1))

__device__ __forceinline__ float2 block_reduce2(float a, float b) {
    __shared__ float2 sh[16];
    int tid = threadIdx.x;
#pragma unroll
    for (int o = 16; o > 0; o >>= 1) {
        a += __shfl_down_sync(0xffffffffu, a, o);
        b += __shfl_down_sync(0xffffffffu, b, o);
    }
    int wid = tid >> 5, lane = tid & 31;
    int nw = blockDim.x >> 5;
    if (lane == 0) sh[wid] = make_float2(a, b);
    __syncthreads();
    if (wid == 0) {
        float2 v = (lane < nw) ? sh[lane] : make_float2(0.f, 0.f);
        a = v.x; b = v.y;
#pragma unroll
        for (int o = 8; o > 0; o >>= 1) {
            a += __shfl_down_sync(0xffffffffu, a, o);
            b += __shfl_down_sync(0xffffffffu, b, o);
        }
        if (lane == 0) sh[0] = make_float2(a, b);
    }
    __syncthreads();
    return sh[0];
}

// -------- fused: fp16 conversion of weights+x AND LN0(x)->fp16 --------
__global__ void conv_ln0(const float* __restrict__ qw, const float* __restrict__ kw,
                         const float* __restrict__ vw, const float* __restrict__ w1,
                         const float* __restrict__ w2, const float* __restrict__ x,
                         const float* __restrict__ ln0w, const float* __restrict__ ln0b,
                         __half* hqw, __half* hkw, __half* hvw, __half* hw1, __half* hw2,
                         __half* hx, __half* xnh)
{
    int t = blockIdx.x;
    int tid = threadIdx.x;
    if (t < 12032) {
        int q = t * 256 + tid;
        const float4* s; __half* d; int off;
        if (q < 32768)        { s = (const float4*)qw; d = hqw; off = q; }
        else if (q < 65536)   { s = (const float4*)kw; d = hkw; off = q - 32768; }
        else if (q < 589824)  { s = (const float4*)vw; d = hvw; off = q - 65536; }
        else if (q < 2686976) { s = (const float4*)w1; d = hw1; off = q - 589824; }
        else if (q < 2949120) { s = (const float4*)w2; d = hw2; off = q - 2686976; }
        else                  { s = (const float4*)x;  d = hx;  off = q - 2949120; }
        float4 v = s[off];
        __half2* d2 = (__half2*)d;
        d2[off * 2]     = __floats2half2_rn(v.x, v.y);
        d2[off * 2 + 1] = __floats2half2_rn(v.z, v.w);
        return;
    }
    int l = t - 12032;
    const float* row = x + (size_t)l * D;
    float v0 = row[tid], v1 = row[tid + 256];
    float2 r = block_reduce2(v0 + v1, v0 * v0 + v1 * v1);
    float mu = r.x * (1.0f / D);
    float var = r.y * (1.0f / D) - mu * mu;
    float rs = rsqrtf(var + 1e-5f);
    xnh[(size_t)l * D + tid]       = __float2half_rn((v0 - mu) * rs * ln0w[tid] + ln0b[tid]);
    xnh[(size_t)l * D + tid + 256] = __float2half_rn((v1 - mu) * rs * ln0w[tid + 256] + ln0b[tid + 256]);
}

// ========== fp16 tensor GEMM mainloop (device fn): 128x128x32 tiles, 4 warps ==========
#define HG_ASTR 40
#define HG_BSTR 136
#define HG_ABYT (128 * HG_ASTR * 2)
#define HG_STG  (HG_ABYT + 32 * HG_BSTR * 2)
#define HG_SMEM (4 * HG_STG)
#define PH_STRIDE (128 * 16 + 8)

__device__ __forceinline__ void hg_main(
    uint32_t sbase, const __half* __restrict__ A, const __half* __restrict__ B,
    int N, int K, int lda, int ldb, int m0, int n0, float (&c)[4][8][4])
{
    int tid = threadIdx.x;
    int wid = tid >> 5, lane = tid & 31;
    int warp_m = wid >> 1, warp_n = wid & 1;
    int kTiles = K / 32;

    const __half* Ab = A + (size_t)(m0 + tid) * lda;
    int br = tid >> 2, bc = (tid & 3) * 32;
    const __half* Bb = B + n0 + bc;

    uint32_t laA = ((lane & 15) * HG_ASTR + ((lane >> 4) << 3)) * 2;
    uint32_t laB = ((lane & 15) * HG_BSTR + ((lane >> 4) << 3)) * 2;
    uint32_t afw = (uint32_t)(warp_m * 64 * HG_ASTR * 2) + laA;
    uint32_t bfw = (uint32_t)(warp_n * 64 * 2) + laB;

#pragma unroll
    for (int i = 0; i < 4; i++)
#pragma unroll
        for (int j = 0; j < 8; j++)
#pragma unroll
            for (int r = 0; r < 4; r++) c[i][j][r] = 0.f;

#pragma unroll
    for (int s = 0; s < 3; s++) {
        if (s < kTiles) {
            uint32_t sA = sbase + s * HG_STG;
            uint32_t sB = sA + HG_ABYT;
#pragma unroll
            for (int cc = 0; cc < 4; cc++)
                cpa16s(sA + (tid * HG_ASTR + cc * 8) * 2, Ab + s * 32 + cc * 8);
#pragma unroll
            for (int cc = 0; cc < 4; cc++)
                cpa16s(sB + (br * HG_BSTR + bc + cc * 8) * 2,
                       Bb + (size_t)(s * 32 + br) * ldb + cc * 8);
        }
        CP_COMMIT();
    }
    CP_WAIT2();
    __syncthreads();

    for (int t = 0; t < kTiles; t++) {
        int tp = t + 3;
        if (tp < kTiles) {
            int ps = tp & 3;
            uint32_t sA = sbase + ps * HG_STG;
            uint32_t sB = sA + HG_ABYT;
#pragma unroll
            for (int cc = 0; cc < 4; cc++)
                cpa16s(sA + (tid * HG_ASTR + cc * 8) * 2, Ab + tp * 32 + cc * 8);
#pragma unroll
            for (int cc = 0; cc < 4; cc++)
                cpa16s(sB + (br * HG_BSTR + bc + cc * 8) * 2,
                       Bb + (size_t)(tp * 32 + br) * ldb + cc * 8);
        }
        CP_COMMIT();

        uint32_t aSt = sbase + (t & 3) * HG_STG + afw;
        uint32_t bSt = sbase + (t & 3) * HG_STG + HG_ABYT + bfw;

        unsigned a[2][4][4], b[2][8][2];
#pragma unroll
        for (int kk = 0; kk < 2; kk++) {
#pragma unroll
            for (int mt = 0; mt < 4; mt++)
                ldsm4(a[kk][mt][0], a[kk][mt][1], a[kk][mt][2], a[kk][mt][3],
                      aSt + (unsigned)((mt * 16 * HG_ASTR + kk * 16) * 2));
#pragma unroll
            for (int p = 0; p < 4; p++) {
                unsigned u0, u1, u2, u3;
                ldsm4t(u0, u1, u2, u3,
                       bSt + (unsigned)((p * 16) * 2 + (kk * 16 * HG_BSTR) * 2));
                b[kk][2 * p][0] = u0;     b[kk][2 * p][1] = u1;
                b[kk][2 * p + 1][0] = u2; b[kk][2 * p + 1][1] = u3;
            }
        }
#pragma unroll
        for (int kk = 0; kk < 2; kk++)
#pragma unroll
            for (int mt = 0; mt < 4; mt++)
#pragma unroll
                for (int nt = 0; nt < 8; nt++)
                    MMA_F16(c[mt][nt][0], c[mt][nt][1], c[mt][nt][2], c[mt][nt][3],
                            a[kk][mt][0], a[kk][mt][1], a[kk][mt][2], a[kk][mt][3],
                            b[kk][nt][0], b[kk][nt][1]);

        CP_WAIT2();
        __syncthreads();
    }
}

template<int EPI>
__device__ __forceinline__ void epi_plain(
    float (&c)[4][8][4], const float* __restrict__ bias,
    float* __restrict__ C, int N, int m0, int n0)
{
    int tid = threadIdx.x;
    int wid = tid >> 5, lane = tid & 31;
    int group = lane >> 2, tg = lane & 3;
    int warp_m = wid >> 1, warp_n = wid & 1;
#pragma unroll
    for (int mt = 0; mt < 4; mt++)
#pragma unroll
        for (int nt = 0; nt < 8; nt++)
#pragma unroll
            for (int r = 0; r < 4; r++) {
                int m = m0 + warp_m * 64 + mt * 16 + group + (r >> 1) * 8;
                int n = n0 + warp_n * 64 + nt * 8 + tg * 2 + (r & 1);
                float v = c[mt][nt][r];
                if (EPI == 2) v = v + bias[n];
                else if (EPI == 3) v = fmaxf(v + bias[n], 0.f);
                C[(size_t)m * N + n] = v;
            }
}

// smem-staged coalesced head-major fp16 store (+bias; EXPE: exp(clip(.)-4))
template<int EXPE>
__device__ __forceinline__ void epi_perm_half(
    float (&c)[4][8][4], char* smemc, const float* __restrict__ bias,
    __half* __restrict__ Ch, int M, int N, int m0, int n0)
{
    int tid = threadIdx.x;
    int wid = tid >> 5, lane = tid & 31;
    int group = lane >> 2, tg = lane & 3;
    int warp_m = wid >> 1, warp_n = wid & 1;
    __syncthreads();
    __half* st = (__half*)smemc;
#pragma unroll
    for (int mt = 0; mt < 4; mt++)
#pragma unroll
        for (int nt = 0; nt < 8; nt++)
#pragma unroll
            for (int r = 0; r < 4; r++) {
                int row = warp_m * 64 + mt * 16 + group + (r >> 1) * 8;
                int n = warp_n * 64 + nt * 8 + tg * 2 + (r & 1);
                float v = c[mt][nt][r] + bias[n0 + n];
                if (EXPE) v = expf(fminf(fmaxf(v, -10.f), 10.f) - 4.0f);
                st[(n & 7) * PH_STRIDE + row * 16 + (n >> 3)] = __float2half_rn(v);
            }
    __syncthreads();
    int NI = N >> 3;
#pragma unroll
    for (int it = 0; it < 16; it++) {
        int cidx = it * 128 + tid;
        int h = cidx >> 8;
        int m = (cidx >> 1) & 127;
        int ck = cidx & 1;
        uint4 v = *(uint4*)&st[h * PH_STRIDE + m * 16 + ck * 8];
        *(uint4*)&Ch[((size_t)(h * M + m0 + m)) * NI + (n0 >> 3) + ck * 8] = v;
    }
}

// ========== fused projection launch: z=1 v-proj (256 CTAs); z=0 q/k direct (4/row) ==========
__global__ void __launch_bounds__(128, 2) fused_proj(
    const __half* __restrict__ hx, const __half* __restrict__ hvw,
    const float* __restrict__ vb, __half* __restrict__ vh,
    const __half* __restrict__ xnh, const __half* __restrict__ hqw,
    const __half* __restrict__ hkw, const float* __restrict__ qb,
    const float* __restrict__ kb, __half* __restrict__ qh, __half* __restrict__ kh)
{
    extern __shared__ char smemc[];
    uint32_t sbase = (uint32_t)__cvta_generic_to_shared(smemc);
    float c[4][8][4];
    int m0 = blockIdx.y * 128;

    if (blockIdx.z == 1) {
        int n0 = blockIdx.x * 128;
        hg_main(sbase, hx, hvw, DH, D, D, DH, m0, n0, c);
        epi_perm_half<0>(c, smemc, vb, vh, L, DH, m0, n0);
    } else {
        int bx = blockIdx.x;
        if (bx >= 4) return;      // before any barrier/cp.async
        int set = bx >> 1;
        int n0 = (bx & 1) * 128;
        const __half* B = set ? hkw : hqw;
        const float* bias = set ? kb : qb;
        __half* O = set ? kh : qh;
        hg_main(sbase, xnh, B, AH, D, D, AH, m0, n0, c);
        epi_perm_half<1>(c, smemc, bias, O, L, AH, m0, n0);
    }
}

// ========== standalone hgemm for FFN (splitK fp32-out) ==========
template<int MODE>
__global__ void __launch_bounds__(128, 2) hgemm(
    const __half* __restrict__ A, const __half* __restrict__ B,
    float* __restrict__ C, int M, int N, int K, int lda, int ldb)
{
    extern __shared__ char smemc[];
    uint32_t sbase = (uint32_t)__cvta_generic_to_shared(smemc);
    int z = blockIdx.z;
    if (MODE == 2) {
        A += (size_t)z * K;
        B += (size_t)z * K * ldb;
        C += (size_t)z * M * N;
    }
    float c[4][8][4];
    int m0 = blockIdx.y * 128, n0 = blockIdx.x * 128;
    hg_main(sbase, A, B, N, K, lda, ldb, m0, n0, c);
    epi_plain<0>(c, nullptr, C, N, m0, n0);
}

// ================= persistent snake-balanced fused flash attention =================
#define AQ_OFF 0
#define AK_OFF 10240
#define AV_OFF 30720
#define AS_OFF 100352
#define ADN_OFF 135168
#define ATTN_SMEM 137216
#define KSTR 40
#define VSTR 136
#define SSTR 136

__global__ void __launch_bounds__(256, 1) attn_kernel(
    const __half* __restrict__ qhp, const __half* __restrict__ khp,
    const __half* __restrict__ vhp, float* __restrict__ qkvh,
    float* __restrict__ den)
{
    extern __shared__ char smc[];
    uint32_t sb = (uint32_t)__cvta_generic_to_shared(smc);
    float* dn = (float*)(smc + ADN_OFF);

    int tid = threadIdx.x, lane = tid & 31, wid = tid >> 5;
    int group = lane >> 2, tg = lane & 3;
    int ws_m = wid >> 2, ws_n = wid & 3;

    uint32_t laK = ((lane & 15) * KSTR + ((lane >> 4) << 3)) * 2;
    uint32_t laV = ((lane & 15) * VSTR + ((lane >> 4) << 3)) * 2;
    uint32_t qfb = sb + AQ_OFF + (uint32_t)(ws_m * 64 * KSTR * 2) + laK;
    uint32_t sfb = sb + AS_OFF + (uint32_t)(ws_m * 64 * SSTR * 2)
                 + ((lane & 15) * SSTR + ((lane >> 4) << 3)) * 2;
    int qr = tid >> 1, qc = (tid & 1) * 16;
    int vr = tid >> 1, vvc = (tid & 1) * 64;

#pragma unroll 1
    for (int slot = 0; slot < 2; slot++) {
        int t = (slot == 0) ? (int)blockIdx.x : 255 - (int)blockIdx.x;
        int i = 7 - (t >> 5);
        int sub = t & 31;
        int h = sub >> 2;
        int d0 = (sub & 3) * 128;

        __syncthreads();

        const __half* Qg = qhp + ((size_t)h * L + i * 128) * DA;
        const __half* Kg = khp + (size_t)h * L * DA;
        const __half* Vg = vhp + (size_t)h * L * D + d0;

        if (tid < 128) { dn[tid] = 0.f; dn[128 + tid] = 0.f; dn[256 + tid] = 0.f; dn[384 + tid] = 0.f; }

        cpa16s(sb + AQ_OFF + (qr * KSTR + qc) * 2,     Qg + qr * DA + qc);
        cpa16s(sb + AQ_OFF + (qr * KSTR + qc + 8) * 2, Qg + qr * DA + qc + 8);
        CP_COMMIT();
        cpa16s(sb + AK_OFF + (qr * KSTR + qc) * 2,     Kg + qr * DA + qc);
        cpa16s(sb + AK_OFF + (qr * KSTR + qc + 8) * 2, Kg + qr * DA + qc + 8);
#pragma unroll
        for (int kk = 0; kk < 8; kk++)
            cpa16s(sb + AV_OFF + (vr * VSTR + vvc + kk * 8) * 2,
                   Vg + (size_t)vr * D + vvc + kk * 8);
        CP_COMMIT();

        float oc[4][4][4];
#pragma unroll
        for (int a = 0; a < 4; a++)
#pragma unroll
            for (int b = 0; b < 4; b++)
#pragma unroll
                for (int r = 0; r < 4; r++) oc[a][b][r] = 0.f;
        float dpart[8];
#pragma unroll
        for (int a = 0; a < 8; a++) dpart[a] = 0.f;

        for (int j = 0; j <= i; j++) {
            int buf = j & 1;
            if (j < i) {
                int nb = buf ^ 1;
                const __half* kg = Kg + (size_t)(j + 1) * 128 * DA;
                const __half* vg = Vg + (size_t)(j + 1) * 128 * D;
                cpa16s(sb + AK_OFF + nb * 10240 + (qr * KSTR + qc) * 2,     kg + qr * DA + qc);
                cpa16s(sb + AK_OFF + nb * 10240 + (qr * KSTR + qc + 8) * 2, kg + qr * DA + qc + 8);
#pragma unroll
                for (int kk = 0; kk < 8; kk++)
                    cpa16s(sb + AV_OFF + nb * 34816 + (vr * VSTR + vvc + kk * 8) * 2,
                           vg + (size_t)vr * D + vvc + kk * 8);
                CP_COMMIT();
                asm volatile("cp.async.wait_group 1;\n" ::: "memory");
            } else {
                asm volatile("cp.async.wait_group 0;\n" ::: "memory");
            }
            __syncthreads();

            float sc[4][4][4];
#pragma unroll
            for (int a = 0; a < 4; a++)
#pragma unroll
                for (int b = 0; b < 4; b++)
#pragma unroll
                    for (int r = 0; r < 4; r++) sc[a][b][r] = 0.f;

            uint32_t kb0 = sb + AK_OFF + (uint32_t)(buf * 10240)
                         + (uint32_t)(ws_n * 32 * KSTR * 2) + laK;
#pragma unroll
            for (int kc = 0; kc < 2; kc++) {
                unsigned qa[4][4], kb[4][2];
#pragma unroll
                for (int mt = 0; mt < 4; mt++)
                    ldsm4(qa[mt][0], qa[mt][1], qa[mt][2], qa[mt][3],
                          qfb + (unsigned)((mt * 16 * KSTR + kc * 16) * 2));
#pragma unroll
                for (int p = 0; p < 2; p++) {
                    unsigned u0, u1, u2, u3;
                    ldsm4(u0, u1, u2, u3, kb0 + (unsigned)((p * 16 * KSTR + kc * 16) * 2));
                    kb[2 * p][0] = u0;     kb[2 * p][1] = u2;
                    kb[2 * p + 1][0] = u1; kb[2 * p + 1][1] = u3;
                }
#pragma unroll
                for (int mt = 0; mt < 4; mt++)
#pragma unroll
                    for (int nt = 0; nt < 4; nt++)
                        MMA_F16(sc[mt][nt][0], sc[mt][nt][1], sc[mt][nt][2], sc[mt][nt][3],
                                qa[mt][0], qa[mt][1], qa[mt][2], qa[mt][3],
                                kb[nt][0], kb[nt][1]);
            }

            bool diag = (j == i);
#pragma unroll
            for (int mt = 0; mt < 4; mt++) {
#pragma unroll
                for (int rp = 0; rp < 2; rp++) {
                    int row = ws_m * 64 + mt * 16 + group + rp * 8;
#pragma unroll
                    for (int nt = 0; nt < 4; nt++) {
                        int colb = ws_n * 32 + nt * 8 + tg * 2;
                        float v0 = sc[mt][nt][rp * 2], v1 = sc[mt][nt][rp * 2 + 1];
                        if (diag) {
                            if (colb > row) v0 = 0.f;
                            if (colb + 1 > row) v1 = 0.f;
                        }
                        __half2 hv = __floats2half2_rn(v0, v1);
                        float2 fb = __half22float2(hv);
                        dpart[mt * 2 + rp] += fb.x + fb.y;
                        *(__half2*)(smc + AS_OFF + ((size_t)row * SSTR + colb) * 2) = hv;
                    }
                }
            }
            __syncthreads();

            uint32_t vb0 = sb + AV_OFF + (uint32_t)(buf * 34816)
                         + (uint32_t)(ws_n * 32 * 2) + laV;
#pragma unroll
            for (int kc = 0; kc < 8; kc++) {
                unsigned sa[4][4], vb[4][2];
#pragma unroll
                for (int mt = 0; mt < 4; mt++)
                    ldsm4(sa[mt][0], sa[mt][1], sa[mt][2], sa[mt][3],
                          sfb + (unsigned)((mt * 16 * SSTR + kc * 16) * 2));
#pragma unroll
                for (int p = 0; p < 2; p++) {
                    unsigned u0, u1, u2, u3;
                    ldsm4t(u0, u1, u2, u3,
                           vb0 + (unsigned)((kc * 16 * VSTR + p * 16) * 2));
                    vb[2 * p][0] = u0;     vb[2 * p][1] = u1;
                    vb[2 * p + 1][0] = u2; vb[2 * p + 1][1] = u3;
                }
#pragma unroll
                for (int mt = 0; mt < 4; mt++)
#pragma unroll
                    for (int nt = 0; nt < 4; nt++)
                        MMA_F16(oc[mt][nt][0], oc[mt][nt][1], oc[mt][nt][2], oc[mt][nt][3],
                                sa[mt][0], sa[mt][1], sa[mt][2], sa[mt][3],
                                vb[nt][0], vb[nt][1]);
            }
            __syncthreads();
        }

#pragma unroll
        for (int mt = 0; mt < 4; mt++)
#pragma unroll
            for (int rp = 0; rp < 2; rp++) {
                int m = i * 128 + ws_m * 64 + mt * 16 + group + rp * 8;
#pragma unroll
                for (int nt = 0; nt < 4; nt++) {
                    int dd = d0 + ws_n * 32 + nt * 8 + tg * 2;
                    *(float2*)&qkvh[((size_t)h * L + m) * D + dd] =
                        make_float2(oc[mt][nt][rp * 2], oc[mt][nt][rp * 2 + 1]);
                }
            }

#pragma unroll
        for (int q = 0; q < 8; q++) {
            float v = dpart[q];
            v += __shfl_xor_sync(0xffffffffu, v, 1, 4);
            v += __shfl_xor_sync(0xffffffffu, v, 2, 4);
            dpart[q] = v;
        }
        if (tg == 0) {
#pragma unroll
            for (int mt = 0; mt < 4; mt++)
#pragma unroll
                for (int rp = 0; rp < 2; rp++) {
                    int row = ws_m * 64 + mt * 16 + group + rp * 8;
                    dn[ws_n * 128 + row] = dpart[mt * 2 + rp];
                }
        }
        __syncthreads();
        if ((sub & 3) == 0 && tid < 128)
            den[h * L + i * 128 + tid] = dn[tid] + dn[128 + tid] + dn[256 + tid] + dn[384 + tid];
    }
}

// -------- y = x + LN1(qkv/den), fp16 output --------
__global__ void y_kernel(const float* __restrict__ x, const float* __restrict__ qkvh,
                         const float* __restrict__ den, const float* __restrict__ w,
                         const float* __restrict__ b, __half* __restrict__ y)
{
    int l = blockIdx.x, tid = threadIdx.x;
    float t[8];
    float s = 0.f, s2 = 0.f;
#pragma unroll
    for (int r = 0; r < 8; r++) {
        int j = tid + r * 512;
        int h = j & 7, d = j >> 3;
        float v = qkvh[((size_t)(h * L + l)) * D + d] / den[h * L + l];
        t[r] = v; s += v; s2 += v * v;
    }
    float2 red = block_reduce2(s, s2);
    float mu = red.x * (1.0f / DH);
    float rs = rsqrtf(red.y * (1.0f / DH) - mu * mu + 1e-5f);
#pragma unroll
    for (int r = 0; r < 8; r++) {
        int j = tid + r * 512;
        y[(size_t)l * DH + j] =
            __float2half_rn(x[(size_t)l * D + (j >> 3)] + (t[r] - mu) * rs * w[j] + b[j]);
    }
}

__global__ void reduce_h1(const float* __restrict__ part, const float* __restrict__ b1,
                          __half* __restrict__ h1)
{
    int q = blockIdx.x * 256 + threadIdx.x;
    const float4* p = (const float4*)part;
    float4 v0 = p[q];
    float4 v1 = p[q + (L * FF / 4)];
    float4 bb = ((const float4*)b1)[q & (FF / 4 - 1)];
    __half2* H = (__half2*)h1;
    H[q * 2]     = __floats2half2_rn(fmaxf(v0.x + v1.x + bb.x, 0.f),
                                     fmaxf(v0.y + v1.y + bb.y, 0.f));
    H[q * 2 + 1] = __floats2half2_rn(fmaxf(v0.z + v1.z + bb.z, 0.f),
                                     fmaxf(v0.w + v1.w + bb.w, 0.f));
}

__global__ void reduce_out(const float* __restrict__ part, const float* __restrict__ b2,
                           const float* __restrict__ x, float* __restrict__ out)
{
    int q = blockIdx.x * 256 + threadIdx.x;
    const float4* p = (const float4*)part;
    float4 v0 = p[q];
    float4 v1 = p[q + 131072];
    float4 v2 = p[q + 262144];
    float4 v3 = p[q + 393216];
    float4 bb = ((const float4*)b2)[q & 127];
    float4 xx = ((const float4*)x)[q];
    float4 o;
    o.x = fmaxf(v0.x + v1.x + v2.x + v3.x + bb.x, 0.f) + xx.x;
    o.y = fmaxf(v0.y + v1.y + v2.y + v3.y + bb.y, 0.f) + xx.y;
    o.z = fmaxf(v0.z + v1.z + v2.z + v3.z + bb.z, 0.f) + xx.z;
    o.w = fmaxf(v0.w + v1.w + v2.w + v3.w + bb.w, 0.f) + xx.w;
    ((float4*)out)[q] = o;
}

extern "C" void kernel_launch(void* const* d_in, const int* in_sizes, int n_in,
                              void* d_out, int out_size)
{
    const float* x    = (const float*)d_in[0];
    const float* ln0w = (const float*)d_in[1];
    const float* ln0b = (const float*)d_in[2];
    const float* ln1w = (const float*)d_in[3];
    const float* ln1b = (const float*)d_in[4];
    const float* qw   = (const float*)d_in[5];
    const float* qb   = (const float*)d_in[6];
    const float* kw   = (const float*)d_in[7];
    const float* kb   = (const float*)d_in[8];
    const float* vw   = (const float*)d_in[9];
    const float* vb   = (const float*)d_in[10];
    const float* w1   = (const float*)d_in[11];
    const float* b1   = (const float*)d_in[12];
    const float* w2   = (const float*)d_in[13];
    const float* b2   = (const float*)d_in[14];
    float* out = (float*)d_out;

    __half *hx, *xnh, *hqw, *hkw, *hvw, *hw1, *hw2, *yh, *h1h, *qh, *kh, *vh;
    float *den, *qkvh, *part, *parth;
    cudaGetSymbolAddress((void**)&hx,    g_hx);
    cudaGetSymbolAddress((void**)&xnh,   g_xnh);
    cudaGetSymbolAddress((void**)&hqw,   g_hqw);
    cudaGetSymbolAddress((void**)&hkw,   g_hkw);
    cudaGetSymbolAddress((void**)&hvw,   g_hvw);
    cudaGetSymbolAddress((void**)&hw1,   g_hw1);
    cudaGetSymbolAddress((void**)&hw2,   g_hw2);
    cudaGetSymbolAddress((void**)&yh,    g_yh);
    cudaGetSymbolAddress((void**)&h1h,   g_h1h);
    cudaGetSymbolAddress((void**)&qh,    g_qh);
    cudaGetSymbolAddress((void**)&kh,    g_kh);
    cudaGetSymbolAddress((void**)&vh,    g_vh);
    cudaGetSymbolAddress((void**)&den,   g_den);
    cudaGetSymbolAddress((void**)&qkvh,  g_qkvh);
    cudaGetSymbolAddress((void**)&part,  g_part);
    cudaGetSymbolAddress((void**)&parth, g_parth);

    cudaFuncSetAttribute(fused_proj, cudaFuncAttributeMaxDynamicSharedMemorySize, HG_SMEM);
    cudaFuncSetAttribute(hgemm<2>, cudaFuncAttributeMaxDynamicSharedMemorySize, HG_SMEM);
    cudaFuncSetAttribute(attn_kernel, cudaFuncAttributeMaxDynamicSharedMemorySize, ATTN_SMEM);

    // 0+1) fused: fp16-convert weights+x, LN0 -> fp16
    conv_ln0<<<13056, 256>>>(qw, kw, vw, w1, w2, x, ln0w, ln0b,
                             hqw, hkw, hvw, hw1, hw2, hx, xnh);
    // 2+3) fused projections: v-proj + direct q/k with exp-perm epilogue
    fused_proj<<<dim3(32, 8, 2), 128, HG_SMEM>>>(
        hx, hvw, vb, vh, xnh, hqw, hkw, qb, kb, qh, kh);
    // 4-6) persistent snake-balanced attention
    attn_kernel<<<128, 256, ATTN_SMEM>>>(qh, kh, vh, qkvh, den);
    // 7) y = x + LN1(qkv/den) -> fp16
    y_kernel<<<L, 512>>>(x, qkvh, den, ln1w, ln1b, yh);
    // 8) h1 partials: splitK=2 of y@w1
    hgemm<2><<<dim3(FF/128, L/128, 2), 128, HG_SMEM>>>(
        yh, hw1, parth, L, FF, DH/2, DH, FF);
    // 8b) h1 = relu(sum + b1) -> fp16
    reduce_h1<<<2048, 256>>>(parth, b1, h1h);
    // 9) w2 partials: splitK=4
    hgemm<2><<<dim3(D/128, L/128, 4), 128, HG_SMEM>>>(
        h1h, hw2, part, L, D, FF/4, FF, D);
    // 10) out = relu(sum+b2)+x
    reduce_out<<<512, 256>>>(part, b2, x, out);
}

// round 16
// speedup vs baseline: 1.3190x; 1.0143x over previous
#include <cuda_runtime.h>
#include <cuda_fp16.h>
#include <math.h>
#include <stdint.h>

#define L  1024
#define D  512
#define NH 8
#define DA 32
#define AH 256
#define DH 4096
#define FF 2048

// -------- scratch --------
__device__ __half g_hx[L * D];
__device__ __half g_xnh[L * D];
__device__ __half g_hqw[D * AH];
__device__ __half g_hkw[D * AH];
__device__ __half g_hvw[D * DH];
__device__ __half g_hw1[DH * FF];
__device__ __half g_hw2[FF * D];
__device__ __half g_yh[(size_t)L * DH];
__device__ __half g_h1h[L * FF];
__device__ __half g_qh[NH * L * DA];
__device__ __half g_kh[NH * L * DA];
__device__ __half g_vh[NH * L * D];
__device__ float g_den[NH * L];
__device__ __half g_qkvh[NH * L * D];
__device__ float g_part[4 * L * D];
__device__ float g_parth[2 * L * FF];

__device__ __forceinline__ void cpa16s(unsigned sa, const void* g) {
    asm volatile("cp.async.cg.shared.global [%0], [%1], 16;\n" :: "r"(sa), "l"(g));
}
#define CP_COMMIT() asm volatile("cp.async.commit_group;\n" ::: "memory")
#define CP_WAIT2()  asm volatile("cp.async.wait_group 2;\n" ::: "memory")

__device__ __forceinline__ void ldsm4(unsigned& r0, unsigned& r1, unsigned& r2, unsigned& r3,
                                      unsigned addr) {
    asm volatile("ldmatrix.sync.aligned.m8n8.x4.shared.b16 {%0,%1,%2,%3}, [%4];"
                 : "=r"(r0), "=r"(r1), "=r"(r2), "=r"(r3) : "r"(addr));
}
__device__ __forceinline__ void ldsm4t(unsigned& r0, unsigned& r1, unsigned& r2, unsigned& r3,
                                       unsigned addr) {
    asm volatile("ldmatrix.sync.aligned.m8n8.x4.trans.shared.b16 {%0,%1,%2,%3}, [%4];"
                 : "=r"(r0), "=r"(r1), "=r"(r2), "=r"(r3) : "r"(addr));
}

#define MMA_F16(c0,c1,c2,c3,a0,a1,a2,a3,b0,b1) \
    asm volatile("mma.sync.aligned.m16n8k16.row.col.f32.f16.f16.f32 " \
        "{%0,%1,%2,%3}, {%4,%5,%6,%7}, {%8,%9}, {%0,%1,%2,%3};" \
        : "+f"(c0), "+f"(c1), "+f"(c2), "+f"(c3) \
        : "r"(a0), "r"(a1), "r"(a2), "r"(a3), "r"(b0), "r"(b1))

__device__ __forceinline__ float2 block_reduce2(float a, float b) {
    __shared__ float2 sh[16];
    int tid = threadIdx.x;
#pragma unroll
    for (int o = 16; o > 0; o >>= 1) {
        a += __shfl_down_sync(0xffffffffu, a, o);
        b += __shfl_down_sync(0xffffffffu, b, o);
    }
    int wid = tid >> 5, lane = tid & 31;
    int nw = blockDim.x >> 5;
    if (lane == 0) sh[wid] = make_float2(a, b);
    __syncthreads();
    if (wid == 0) {
        float2 v = (lane < nw) ? sh[lane] : make_float2(0.f, 0.f);
        a = v.x; b = v.y;
#pragma unroll
        for (int o = 8; o > 0; o >>= 1) {
            a += __shfl_down_sync(0xffffffffu, a, o);
            b += __shfl_down_sync(0xffffffffu, b, o);
        }
        if (lane == 0) sh[0] = make_float2(a, b);
    }
    __syncthreads();
    return sh[0];
}

// -------- fused: fp16 conversion of weights+x AND LN0(x)->fp16 --------
__global__ void conv_ln0(const float* __restrict__ qw, const float* __restrict__ kw,
                         const float* __restrict__ vw, const float* __restrict__ w1,
                         const float* __restrict__ w2, const float* __restrict__ x,
                         const float* __restrict__ ln0w, const float* __restrict__ ln0b,
                         __half* hqw, __half* hkw, __half* hvw, __half* hw1, __half* hw2,
                         __half* hx, __half* xnh)
{
    int t = blockIdx.x;
    int tid = threadIdx.x;
    if (t < 12032) {
        int q = t * 256 + tid;
        const float4* s; __half* d; int off;
        if (q < 32768)        { s = (const float4*)qw; d = hqw; off = q; }
        else if (q < 65536)   { s = (const float4*)kw; d = hkw; off = q - 32768; }
        else if (q < 589824)  { s = (const float4*)vw; d = hvw; off = q - 65536; }
        else if (q < 2686976) { s = (const float4*)w1; d = hw1; off = q - 589824; }
        else if (q < 2949120) { s = (const float4*)w2; d = hw2; off = q - 2686976; }
        else                  { s = (const float4*)x;  d = hx;  off = q - 2949120; }
        float4 v = s[off];
        __half2* d2 = (__half2*)d;
        d2[off * 2]     = __floats2half2_rn(v.x, v.y);
        d2[off * 2 + 1] = __floats2half2_rn(v.z, v.w);
        return;
    }
    int l = t - 12032;
    const float* row = x + (size_t)l * D;
    float v0 = row[tid], v1 = row[tid + 256];
    float2 r = block_reduce2(v0 + v1, v0 * v0 + v1 * v1);
    float mu = r.x * (1.0f / D);
    float var = r.y * (1.0f / D) - mu * mu;
    float rs = rsqrtf(var + 1e-5f);
    xnh[(size_t)l * D + tid]       = __float2half_rn((v0 - mu) * rs * ln0w[tid] + ln0b[tid]);
    xnh[(size_t)l * D + tid + 256] = __float2half_rn((v1 - mu) * rs * ln0w[tid + 256] + ln0b[tid + 256]);
}

// ========== fp16 tensor GEMM mainloop (device fn): 128x128x32 tiles, 4 warps ==========
#define HG_ASTR 40
#define HG_BSTR 136
#define HG_ABYT (128 * HG_ASTR * 2)
#define HG_STG  (HG_ABYT + 32 * HG_BSTR * 2)
#define HG_SMEM (4 * HG_STG)
#define PH_STRIDE (128 * 16 + 8)

__device__ __forceinline__ void hg_main(
    uint32_t sbase, const __half* __restrict__ A, const __half* __restrict__ B,
    int N, int K, int lda, int ldb, int m0, int n0, float (&c)[4][8][4])
{
    int tid = threadIdx.x;
    int wid = tid >> 5, lane = tid & 31;
    int warp_m = wid >> 1, warp_n = wid & 1;
    int kTiles = K / 32;

    const __half* Ab = A + (size_t)(m0 + tid) * lda;
    int br = tid >> 2, bc = (tid & 3) * 32;
    const __half* Bb = B + n0 + bc;

    uint32_t laA = ((lane & 15) * HG_ASTR + ((lane >> 4) << 3)) * 2;
    uint32_t laB = ((lane & 15) * HG_BSTR + ((lane >> 4) << 3)) * 2;
    uint32_t afw = (uint32_t)(warp_m * 64 * HG_ASTR * 2) + laA;
    uint32_t bfw = (uint32_t)(warp_n * 64 * 2) + laB;

#pragma unroll
    for (int i = 0; i < 4; i++)
#pragma unroll
        for (int j = 0; j < 8; j++)
#pragma unroll
            for (int r = 0; r < 4; r++) c[i][j][r] = 0.f;

#pragma unroll
    for (int s = 0; s < 3; s++) {
        if (s < kTiles) {
            uint32_t sA = sbase + s * HG_STG;
            uint32_t sB = sA + HG_ABYT;
#pragma unroll
            for (int cc = 0; cc < 4; cc++)
                cpa16s(sA + (tid * HG_ASTR + cc * 8) * 2, Ab + s * 32 + cc * 8);
#pragma unroll
            for (int cc = 0; cc < 4; cc++)
                cpa16s(sB + (br * HG_BSTR + bc + cc * 8) * 2,
                       Bb + (size_t)(s * 32 + br) * ldb + cc * 8);
        }
        CP_COMMIT();
    }
    CP_WAIT2();
    __syncthreads();

    for (int t = 0; t < kTiles; t++) {
        int tp = t + 3;
        if (tp < kTiles) {
            int ps = tp & 3;
            uint32_t sA = sbase + ps * HG_STG;
            uint32_t sB = sA + HG_ABYT;
#pragma unroll
            for (int cc = 0; cc < 4; cc++)
                cpa16s(sA + (tid * HG_ASTR + cc * 8) * 2, Ab + tp * 32 + cc * 8);
#pragma unroll
            for (int cc = 0; cc < 4; cc++)
                cpa16s(sB + (br * HG_BSTR + bc + cc * 8) * 2,
                       Bb + (size_t)(tp * 32 + br) * ldb + cc * 8);
        }
        CP_COMMIT();

        uint32_t aSt = sbase + (t & 3) * HG_STG + afw;
        uint32_t bSt = sbase + (t & 3) * HG_STG + HG_ABYT + bfw;

        unsigned a[2][4][4], b[2][8][2];
#pragma unroll
        for (int kk = 0; kk < 2; kk++) {
#pragma unroll
            for (int mt = 0; mt < 4; mt++)
                ldsm4(a[kk][mt][0], a[kk][mt][1], a[kk][mt][2], a[kk][mt][3],
                      aSt + (unsigned)((mt * 16 * HG_ASTR + kk * 16) * 2));
#pragma unroll
            for (int p = 0; p < 4; p++) {
                unsigned u0, u1, u2, u3;
                ldsm4t(u0, u1, u2, u3,
                       bSt + (unsigned)((p * 16) * 2 + (kk * 16 * HG_BSTR) * 2));
                b[kk][2 * p][0] = u0;     b[kk][2 * p][1] = u1;
                b[kk][2 * p + 1][0] = u2; b[kk][2 * p + 1][1] = u3;
            }
        }
#pragma unroll
        for (int kk = 0; kk < 2; kk++)
#pragma unroll
            for (int mt = 0; mt < 4; mt++)
#pragma unroll
                for (int nt = 0; nt < 8; nt++)
                    MMA_F16(c[mt][nt][0], c[mt][nt][1], c[mt][nt][2], c[mt][nt][3],
                            a[kk][mt][0], a[kk][mt][1], a[kk][mt][2], a[kk][mt][3],
                            b[kk][nt][0], b[kk][nt][1]);

        CP_WAIT2();
        __syncthreads();
    }
}

template<int EPI>
__device__ __forceinline__ void epi_plain(
    float (&c)[4][8][4], const float* __restrict__ bias,
    float* __restrict__ C, int N, int m0, int n0)
{
    int tid = threadIdx.x;
    int wid = tid >> 5, lane = tid & 31;
    int group = lane >> 2, tg = lane & 3;
    int warp_m = wid >> 1, warp_n = wid & 1;
#pragma unroll
    for (int mt = 0; mt < 4; mt++)
#pragma unroll
        for (int nt = 0; nt < 8; nt++)
#pragma unroll
            for (int r = 0; r < 4; r++) {
                int m = m0 + warp_m * 64 + mt * 16 + group + (r >> 1) * 8;
                int n = n0 + warp_n * 64 + nt * 8 + tg * 2 + (r & 1);
                float v = c[mt][nt][r];
                if (EPI == 2) v = v + bias[n];
                else if (EPI == 3) v = fmaxf(v + bias[n], 0.f);
                C[(size_t)m * N + n] = v;
            }
}

template<int EXPE>
__device__ __forceinline__ void epi_perm_half(
    float (&c)[4][8][4], char* smemc, const float* __restrict__ bias,
    __half* __restrict__ Ch, int M, int N, int m0, int n0)
{
    int tid = threadIdx.x;
    int wid = tid >> 5, lane = tid & 31;
    int group = lane >> 2, tg = lane & 3;
    int warp_m = wid >> 1, warp_n = wid & 1;
    __syncthreads();
    __half* st = (__half*)smemc;
#pragma unroll
    for (int mt = 0; mt < 4; mt++)
#pragma unroll
        for (int nt = 0; nt < 8; nt++)
#pragma unroll
            for (int r = 0; r < 4; r++) {
                int row = warp_m * 64 + mt * 16 + group + (r >> 1) * 8;
                int n = warp_n * 64 + nt * 8 + tg * 2 + (r & 1);
                float v = c[mt][nt][r] + bias[n0 + n];
                if (EXPE) v = expf(fminf(fmaxf(v, -10.f), 10.f) - 4.0f);
                st[(n & 7) * PH_STRIDE + row * 16 + (n >> 3)] = __float2half_rn(v);
            }
    __syncthreads();
    int NI = N >> 3;
#pragma unroll
    for (int it = 0; it < 16; it++) {
        int cidx = it * 128 + tid;
        int h = cidx >> 8;
        int m = (cidx >> 1) & 127;
        int ck = cidx & 1;
        uint4 v = *(uint4*)&st[h * PH_STRIDE + m * 16 + ck * 8];
        *(uint4*)&Ch[((size_t)(h * M + m0 + m)) * NI + (n0 >> 3) + ck * 8] = v;
    }
}

// ========== fused projection launch ==========
__global__ void __launch_bounds__(128, 2) fused_proj(
    const __half* __restrict__ hx, const __half* __restrict__ hvw,
    const float* __restrict__ vb, __half* __restrict__ vh,
    const __half* __restrict__ xnh, const __half* __restrict__ hqw,
    const __half* __restrict__ hkw, const float* __restrict__ qb,
    const float* __restrict__ kb, __half* __restrict__ qh, __half* __restrict__ kh)
{
    extern __shared__ char smemc[];
    uint32_t sbase = (uint32_t)__cvta_generic_to_shared(smemc);
    float c[4][8][4];
    int m0 = blockIdx.y * 128;

    if (blockIdx.z == 1) {
        int n0 = blockIdx.x * 128;
        hg_main(sbase, hx, hvw, DH, D, D, DH, m0, n0, c);
        epi_perm_half<0>(c, smemc, vb, vh, L, DH, m0, n0);
    } else {
        int bx = blockIdx.x;
        if (bx >= 4) return;
        int set = bx >> 1;
        int n0 = (bx & 1) * 128;
        const __half* B = set ? hkw : hqw;
        const float* bias = set ? kb : qb;
        __half* O = set ? kh : qh;
        hg_main(sbase, xnh, B, AH, D, D, AH, m0, n0, c);
        epi_perm_half<1>(c, smemc, bias, O, L, AH, m0, n0);
    }
}

// ========== standalone hgemm for FFN (splitK fp32-out) ==========
template<int MODE>
__global__ void __launch_bounds__(128, 2) hgemm(
    const __half* __restrict__ A, const __half* __restrict__ B,
    float* __restrict__ C, int M, int N, int K, int lda, int ldb)
{
    extern __shared__ char smemc[];
    uint32_t sbase = (uint32_t)__cvta_generic_to_shared(smemc);
    int z = blockIdx.z;
    if (MODE == 2) {
        A += (size_t)z * K;
        B += (size_t)z * K * ldb;
        C += (size_t)z * M * N;
    }
    float c[4][8][4];
    int m0 = blockIdx.y * 128, n0 = blockIdx.x * 128;
    hg_main(sbase, A, B, N, K, lda, ldb, m0, n0, c);
    epi_plain<0>(c, nullptr, C, N, m0, n0);
}

// ================= persistent snake-balanced fused flash attention =================
#define AQ_OFF 0
#define AK_OFF 10240
#define AV_OFF 30720
#define AS_OFF 100352
#define ADN_OFF 135168
#define ATTN_SMEM 137216
#define KSTR 40
#define VSTR 136
#define SSTR 136

__global__ void __launch_bounds__(256, 1) attn_kernel(
    const __half* __restrict__ qhp, const __half* __restrict__ khp,
    const __half* __restrict__ vhp, __half* __restrict__ qkvh,
    float* __restrict__ den)
{
    extern __shared__ char smc[];
    uint32_t sb = (uint32_t)__cvta_generic_to_shared(smc);
    float* dn = (float*)(smc + ADN_OFF);

    int tid = threadIdx.x, lane = tid & 31, wid = tid >> 5;
    int group = lane >> 2, tg = lane & 3;
    int ws_m = wid >> 2, ws_n = wid & 3;

    uint32_t laK = ((lane & 15) * KSTR + ((lane >> 4) << 3)) * 2;
    uint32_t laV = ((lane & 15) * VSTR + ((lane >> 4) << 3)) * 2;
    uint32_t qfb = sb + AQ_OFF + (uint32_t)(ws_m * 64 * KSTR * 2) + laK;
    uint32_t sfb = sb + AS_OFF + (uint32_t)(ws_m * 64 * SSTR * 2)
                 + ((lane & 15) * SSTR + ((lane >> 4) << 3)) * 2;
    int qr = tid >> 1, qc = (tid & 1) * 16;
    int vr = tid >> 1, vvc = (tid & 1) * 64;

#pragma unroll 1
    for (int slot = 0; slot < 2; slot++) {
        int t = (slot == 0) ? (int)blockIdx.x : 255 - (int)blockIdx.x;
        int i = 7 - (t >> 5);
        int sub = t & 31;
        int h = sub >> 2;
        int d0 = (sub & 3) * 128;

        __syncthreads();

        const __half* Qg = qhp + ((size_t)h * L + i * 128) * DA;
        const __half* Kg = khp + (size_t)h * L * DA;
        const __half* Vg = vhp + (size_t)h * L * D + d0;

        if (tid < 128) { dn[tid] = 0.f; dn[128 + tid] = 0.f; dn[256 + tid] = 0.f; dn[384 + tid] = 0.f; }

        cpa16s(sb + AQ_OFF + (qr * KSTR + qc) * 2,     Qg + qr * DA + qc);
        cpa16s(sb + AQ_OFF + (qr * KSTR + qc + 8) * 2, Qg + qr * DA + qc + 8);
        CP_COMMIT();
        cpa16s(sb + AK_OFF + (qr * KSTR + qc) * 2,     Kg + qr * DA + qc);
        cpa16s(sb + AK_OFF + (qr * KSTR + qc + 8) * 2, Kg + qr * DA + qc + 8);
#pragma unroll
        for (int kk = 0; kk < 8; kk++)
            cpa16s(sb + AV_OFF + (vr * VSTR + vvc + kk * 8) * 2,
                   Vg + (size_t)vr * D + vvc + kk * 8);
        CP_COMMIT();

        float oc[4][4][4];
#pragma unroll
        for (int a = 0; a < 4; a++)
#pragma unroll
            for (int b = 0; b < 4; b++)
#pragma unroll
                for (int r = 0; r < 4; r++) oc[a][b][r] = 0.f;
        float dpart[8];
#pragma unroll
        for (int a = 0; a < 8; a++) dpart[a] = 0.f;

        for (int j = 0; j <= i; j++) {
            int buf = j & 1;
            if (j < i) {
                int nb = buf ^ 1;
                const __half* kg = Kg + (size_t)(j + 1) * 128 * DA;
                const __half* vg = Vg + (size_t)(j + 1) * 128 * D;
                cpa16s(sb + AK_OFF + nb * 10240 + (qr * KSTR + qc) * 2,     kg + qr * DA + qc);
                cpa16s(sb + AK_OFF + nb * 10240 + (qr * KSTR + qc + 8) * 2, kg + qr * DA + qc + 8);
#pragma unroll
                for (int kk = 0; kk < 8; kk++)
                    cpa16s(sb + AV_OFF + nb * 34816 + (vr * VSTR + vvc + kk * 8) * 2,
                           vg + (size_t)vr * D + vvc + kk * 8);
                CP_COMMIT();
                asm volatile("cp.async.wait_group 1;\n" ::: "memory");
            } else {
                asm volatile("cp.async.wait_group 0;\n" ::: "memory");
            }
            __syncthreads();

            float sc[4][4][4];
#pragma unroll
            for (int a = 0; a < 4; a++)
#pragma unroll
                for (int b = 0; b < 4; b++)
#pragma unroll
                    for (int r = 0; r < 4; r++) sc[a][b][r] = 0.f;

            uint32_t kb0 = sb + AK_OFF + (uint32_t)(buf * 10240)
                         + (uint32_t)(ws_n * 32 * KSTR * 2) + laK;
#pragma unroll
            for (int kc = 0; kc < 2; kc++) {
                unsigned qa[4][4], kb[4][2];
#pragma unroll
                for (int mt = 0; mt < 4; mt++)
                    ldsm4(qa[mt][0], qa[mt][1], qa[mt][2], qa[mt][3],
                          qfb + (unsigned)((mt * 16 * KSTR + kc * 16) * 2));
#pragma unroll
                for (int p = 0; p < 2; p++) {
                    unsigned u0, u1, u2, u3;
                    ldsm4(u0, u1, u2, u3, kb0 + (unsigned)((p * 16 * KSTR + kc * 16) * 2));
                    kb[2 * p][0] = u0;     kb[2 * p][1] = u2;
                    kb[2 * p + 1][0] = u1; kb[2 * p + 1][1] = u3;
                }
#pragma unroll
                for (int mt = 0; mt < 4; mt++)
#pragma unroll
                    for (int nt = 0; nt < 4; nt++)
                        MMA_F16(sc[mt][nt][0], sc[mt][nt][1], sc[mt][nt][2], sc[mt][nt][3],
                                qa[mt][0], qa[mt][1], qa[mt][2], qa[mt][3],
                                kb[nt][0], kb[nt][1]);
            }

            bool diag = (j == i);
#pragma unroll
            for (int mt = 0; mt < 4; mt++) {
#pragma unroll
                for (int rp = 0; rp < 2; rp++) {
                    int row = ws_m * 64 + mt * 16 + group + rp * 8;
#pragma unroll
                    for (int nt = 0; nt < 4; nt++) {
                        int colb = ws_n * 32 + nt * 8 + tg * 2;
                        float v0 = sc[mt][nt][rp * 2], v1 = sc[mt][nt][rp * 2 + 1];
                        if (diag) {
                            if (colb > row) v0 = 0.f;
                            if (colb + 1 > row) v1 = 0.f;
                        }
                        __half2 hv = __floats2half2_rn(v0, v1);
                        float2 fb = __half22float2(hv);
                        dpart[mt * 2 + rp] += fb.x + fb.y;
                        *(__half2*)(smc + AS_OFF + ((size_t)row * SSTR + colb) * 2) = hv;
                    }
                }
            }
            __syncthreads();

            uint32_t vb0 = sb + AV_OFF + (uint32_t)(buf * 34816)
                         + (uint32_t)(ws_n * 32 * 2) + laV;
#pragma unroll
            for (int kc = 0; kc < 8; kc++) {
                unsigned sa[4][4], vb[4][2];
#pragma unroll
                for (int mt = 0; mt < 4; mt++)
                    ldsm4(sa[mt][0], sa[mt][1], sa[mt][2], sa[mt][3],
                          sfb + (unsigned)((mt * 16 * SSTR + kc * 16) * 2));
#pragma unroll
                for (int p = 0; p < 2; p++) {
                    unsigned u0, u1, u2, u3;
                    ldsm4t(u0, u1, u2, u3,
                           vb0 + (unsigned)((kc * 16 * VSTR + p * 16) * 2));
                    vb[2 * p][0] = u0;     vb[2 * p][1] = u1;
                    vb[2 * p + 1][0] = u2; vb[2 * p + 1][1] = u3;
                }
#pragma unroll
                for (int mt = 0; mt < 4; mt++)
#pragma unroll
                    for (int nt = 0; nt < 4; nt++)
                        MMA_F16(oc[mt][nt][0], oc[mt][nt][1], oc[mt][nt][2], oc[mt][nt][3],
                                sa[mt][0], sa[mt][1], sa[mt][2], sa[mt][3],
                                vb[nt][0], vb[nt][1]);
            }
            __syncthreads();
        }

#pragma unroll
        for (int mt = 0; mt < 4; mt++)
#pragma unroll
            for (int rp = 0; rp < 2; rp++) {
                int m = i * 128 + ws_m * 64 + mt * 16 + group + rp * 8;
#pragma unroll
                for (int nt = 0; nt < 4; nt++) {
                    int dd = d0 + ws_n * 32 + nt * 8 + tg * 2;
                    *(__half2*)&qkvh[((size_t)h * L + m) * D + dd] =
                        __floats2half2_rn(oc[mt][nt][rp * 2], oc[mt][nt][rp * 2 + 1]);
                }
            }

#pragma unroll
        for (int q = 0; q < 8; q++) {
            float v = dpart[q];
            v += __shfl_xor_sync(0xffffffffu, v, 1, 4);
            v += __shfl_xor_sync(0xffffffffu, v, 2, 4);
            dpart[q] = v;
        }
        if (tg == 0) {
#pragma unroll
            for (int mt = 0; mt < 4; mt++)
#pragma unroll
                for (int rp = 0; rp < 2; rp++) {
                    int row = ws_m * 64 + mt * 16 + group + rp * 8;
                    dn[ws_n * 128 + row] = dpart[mt * 2 + rp];
                }
        }
        __syncthreads();
        if ((sub & 3) == 0 && tid < 128)
            den[h * L + i * 128 + tid] = dn[tid] + dn[128 + tid] + dn[256 + tid] + dn[384 + tid];
    }
}

// -------- y = x + LN1(qkv/den): coalesced smem-staged, fp16 in/out --------
#define YSTR 516
__global__ void __launch_bounds__(512) y_kernel(
    const float* __restrict__ x, const __half* __restrict__ qkvh,
    const float* __restrict__ den, const float* __restrict__ w,
    const float* __restrict__ b, __half* __restrict__ y)
{
    __shared__ float smq[8 * YSTR];
    __shared__ float rdn[8];
    int l = blockIdx.x, tid = threadIdx.x;

    // phase 1: coalesced load of the full [8][512] qkv row into smem
    int h = tid >> 6, dbase = (tid & 63) * 8;
    uint4 raw = *(const uint4*)&qkvh[((size_t)(h * L + l)) * D + dbase];
    const __half2* hp = (const __half2*)&raw;
#pragma unroll
    for (int e = 0; e < 4; e++) {
        float2 f = __half22float2(hp[e]);
        smq[h * YSTR + dbase + e * 2]     = f.x;
        smq[h * YSTR + dbase + e * 2 + 1] = f.y;
    }
    if (tid < 8) rdn[tid] = 1.0f / den[tid * L + l];
    __syncthreads();

    float t[8];
    float s = 0.f, s2 = 0.f;
#pragma unroll
    for (int r = 0; r < 8; r++) {
        int j = tid + r * 512;
        int hh = j & 7, d = j >> 3;
        float v = smq[hh * YSTR + d] * rdn[hh];
        t[r] = v; s += v; s2 += v * v;
    }
    float2 red = block_reduce2(s, s2);
    float mu = red.x * (1.0f / DH);
    float rs = rsqrtf(red.y * (1.0f / DH) - mu * mu + 1e-5f);
#pragma unroll
    for (int r = 0; r < 8; r++) {
        int j = tid + r * 512;
        y[(size_t)l * DH + j] =
            __float2half_rn(x[(size_t)l * D + (j >> 3)] + (t[r] - mu) * rs * w[j] + b[j]);
    }
}

__global__ void reduce_h1(const float* __restrict__ part, const float* __restrict__ b1,
                          __half* __restrict__ h1)
{
    int q = blockIdx.x * 256 + threadIdx.x;
    const float4* p = (const float4*)part;
    float4 v0 = p[q];
    float4 v1 = p[q + (L * FF / 4)];
    float4 bb = ((const float4*)b1)[q & (FF / 4 - 1)];
    __half2* H = (__half2*)h1;
    H[q * 2]     = __floats2half2_rn(fmaxf(v0.x + v1.x + bb.x, 0.f),
                                     fmaxf(v0.y + v1.y + bb.y, 0.f));
    H[q * 2 + 1] = __floats2half2_rn(fmaxf(v0.z + v1.z + bb.z, 0.f),
                                     fmaxf(v0.w + v1.w + bb.w, 0.f));
}

__global__ void reduce_out(const float* __restrict__ part, const float* __restrict__ b2,
                           const float* __restrict__ x, float* __restrict__ out)
{
    int q = blockIdx.x * 256 + threadIdx.x;
    const float4* p = (const float4*)part;
    float4 v0 = p[q];
    float4 v1 = p[q + 131072];
    float4 v2 = p[q + 262144];
    float4 v3 = p[q + 393216];
    float4 bb = ((const float4*)b2)[q & 127];
    float4 xx = ((const float4*)x)[q];
    float4 o;
    o.x = fmaxf(v0.x + v1.x + v2.x + v3.x + bb.x, 0.f) + xx.x;
    o.y = fmaxf(v0.y + v1.y + v2.y + v3.y + bb.y, 0.f) + xx.y;
    o.z = fmaxf(v0.z + v1.z + v2.z + v3.z + bb.z, 0.f) + xx.z;
    o.w = fmaxf(v0.w + v1.w + v2.w + v3.w + bb.w, 0.f) + xx.w;
    ((float4*)out)[q] = o;
}

extern "C" void kernel_launch(void* const* d_in, const int* in_sizes, int n_in,
                              void* d_out, int out_size)
{
    const float* x    = (const float*)d_in[0];
    const float* ln0w = (const float*)d_in[1];
    const float* ln0b = (const float*)d_in[2];
    const float* ln1w = (const float*)d_in[3];
    const float* ln1b = (const float*)d_in[4];
    const float* qw   = (const float*)d_in[5];
    const float* qb   = (const float*)d_in[6];
    const float* kw   = (const float*)d_in[7];
    const float* kb   = (const float*)d_in[8];
    const float* vw   = (const float*)d_in[9];
    const float* vb   = (const float*)d_in[10];
    const float* w1   = (const float*)d_in[11];
    const float* b1   = (const float*)d_in[12];
    const float* w2   = (const float*)d_in[13];
    const float* b2   = (const float*)d_in[14];
    float* out = (float*)d_out;

    __half *hx, *xnh, *hqw, *hkw, *hvw, *hw1, *hw2, *yh, *h1h, *qh, *kh, *vh, *qkvh;
    float *den, *part, *parth;
    cudaGetSymbolAddress((void**)&hx,    g_hx);
    cudaGetSymbolAddress((void**)&xnh,   g_xnh);
    cudaGetSymbolAddress((void**)&hqw,   g_hqw);
    cudaGetSymbolAddress((void**)&hkw,   g_hkw);
    cudaGetSymbolAddress((void**)&hvw,   g_hvw);
    cudaGetSymbolAddress((void**)&hw1,   g_hw1);
    cudaGetSymbolAddress((void**)&hw2,   g_hw2);
    cudaGetSymbolAddress((void**)&yh,    g_yh);
    cudaGetSymbolAddress((void**)&h1h,   g_h1h);
    cudaGetSymbolAddress((void**)&qh,    g_qh);
    cudaGetSymbolAddress((void**)&kh,    g_kh);
    cudaGetSymbolAddress((void**)&vh,    g_vh);
    cudaGetSymbolAddress((void**)&den,   g_den);
    cudaGetSymbolAddress((void**)&qkvh,  g_qkvh);
    cudaGetSymbolAddress((void**)&part,  g_part);
    cudaGetSymbolAddress((void**)&parth, g_parth);

    cudaFuncSetAttribute(fused_proj, cudaFuncAttributeMaxDynamicSharedMemorySize, HG_SMEM);
    cudaFuncSetAttribute(hgemm<2>, cudaFuncAttributeMaxDynamicSharedMemorySize, HG_SMEM);
    cudaFuncSetAttribute(attn_kernel, cudaFuncAttributeMaxDynamicSharedMemorySize, ATTN_SMEM);

    // 0+1) fused: fp16-convert weights+x, LN0 -> fp16
    conv_ln0<<<13056, 256>>>(qw, kw, vw, w1, w2, x, ln0w, ln0b,
                             hqw, hkw, hvw, hw1, hw2, hx, xnh);
    // 2+3) fused projections
    fused_proj<<<dim3(32, 8, 2), 128, HG_SMEM>>>(
        hx, hvw, vb, vh, xnh, hqw, hkw, qb, kb, qh, kh);
    // 4-6) persistent snake-balanced attention (fp16 qkv out)
    attn_kernel<<<128, 256, ATTN_SMEM>>>(qh, kh, vh, qkvh, den);
    // 7) y = x + LN1(qkv/den) -> fp16 (coalesced staged)
    y_kernel<<<L, 512>>>(x, qkvh, den, ln1w, ln1b, yh);
    // 8) h1 partials: splitK=2 of y@w1
    hgemm<2><<<dim3(FF/128, L/128, 2), 128, HG_SMEM>>>(
        yh, hw1, parth, L, FF, DH/2, DH, FF);
    // 8b) h1 = relu(sum + b1) -> fp16
    reduce_h1<<<2048, 256>>>(parth, b1, h1h);
    // 9) w2 partials: splitK=4
    hgemm<2><<<dim3(D/128, L/128, 4), 128, HG_SMEM>>>(
        h1h, hw2, part, L, D, FF/4, FF, D);
    // 10) out = relu(sum+b2)+x
    reduce_out<<<512, 256>>>(part, b2, x, out);
}